// round 5
// baseline (speedup 1.0000x reference)
#include <cuda_runtime.h>
#include <cstdint>

#define N_NODE 100000
#define N_TOT  102000
#define NFEAT  256
#define NDIM   128
#define CAP    64
#define SPILL_MAX 8192

// ---------------------------------------------------------------------------
// Device scratch: ELL bins for both adjacencies + spill safety net
// ---------------------------------------------------------------------------
__device__ int                g_cnt[2][N_TOT];
__device__ unsigned long long g_rec[2][(size_t)N_TOT * CAP];
__device__ int                g_spill_cnt;
__device__ int4               g_spill[SPILL_MAX];   // {row | a<<30, col, valbits, -}

// ---------------------------------------------------------------------------
__global__ void zero_cnt_kernel() {
    int i = blockIdx.x * blockDim.x + threadIdx.x;
    int n = 2 * N_TOT;
    int stride = gridDim.x * blockDim.x;
    for (int j = i; j < n; j += stride)
        ((int*)g_cnt)[j] = 0;
    if (i == 0) g_spill_cnt = 0;
}

// ---------------------------------------------------------------------------
// ELL placement: one pass, 8 edges/thread, both adjacencies
// ---------------------------------------------------------------------------
__global__ __launch_bounds__(256) void place_kernel(
    const int* __restrict__ erow1, const int* __restrict__ ecol1, const float* __restrict__ eval1,
    const int* __restrict__ erow2, const int* __restrict__ ecol2, const float* __restrict__ eval2,
    int E, int perAdj)
{
    int idx = blockIdx.x * blockDim.x + threadIdx.x;
    int a = 0;
    if (idx >= perAdj) { a = 1; idx -= perAdj; if (idx >= perAdj) return; }
    const int*   erow = a ? erow2 : erow1;
    const int*   ecol = a ? ecol2 : ecol1;
    const float* eval = a ? eval2 : eval1;
    unsigned long long* rec = g_rec[a];
    int* cnt = g_cnt[a];

    int e0 = idx * 8;
    int nn = (e0 + 8 <= E) ? 8 : (E - e0);
    if (nn <= 0) return;

    int rr[8], cc[8]; float vv[8];
#pragma unroll
    for (int q = 0; q < 2; q++) {
        if (e0 + q * 4 + 4 <= E) {
            int4   r4 = *(const int4*)(erow + e0 + q * 4);
            int4   c4 = *(const int4*)(ecol + e0 + q * 4);
            float4 v4 = *(const float4*)(eval + e0 + q * 4);
            rr[q*4+0] = r4.x; rr[q*4+1] = r4.y; rr[q*4+2] = r4.z; rr[q*4+3] = r4.w;
            cc[q*4+0] = c4.x; cc[q*4+1] = c4.y; cc[q*4+2] = c4.z; cc[q*4+3] = c4.w;
            vv[q*4+0] = v4.x; vv[q*4+1] = v4.y; vv[q*4+2] = v4.z; vv[q*4+3] = v4.w;
        } else {
            for (int i = q * 4; i < nn; i++) {
                rr[i] = __ldg(erow + e0 + i);
                cc[i] = __ldg(ecol + e0 + i);
                vv[i] = __ldg(eval + e0 + i);
            }
        }
    }

    int pos[8];
#pragma unroll
    for (int i = 0; i < 8; i++)
        if (i < nn) pos[i] = atomicAdd(&cnt[rr[i]], 1);

#pragma unroll
    for (int i = 0; i < 8; i++) {
        if (i < nn) {
            unsigned long long r8 = (unsigned long long)(unsigned)cc[i]
                                  | ((unsigned long long)__float_as_uint(vv[i]) << 32);
            if (pos[i] < CAP) {
                rec[(size_t)rr[i] * CAP + pos[i]] = r8;
            } else {
                int s = atomicAdd(&g_spill_cnt, 1);
                if (s < SPILL_MAX)
                    g_spill[s] = make_int4(rr[i] | (a << 30), cc[i],
                                           (int)__float_as_uint(vv[i]), 0);
            }
        }
    }
}

// ---------------------------------------------------------------------------
// SpMM from ELL: one warp per output row. Records loaded once into lanes
// (1-2 LDG per warp), broadcast via shfl; gathers in batches of 8 (MLP=8).
// ---------------------------------------------------------------------------
__global__ __launch_bounds__(256) void spmm_kernel(
    const float* __restrict__ x1, float* __restrict__ x2, float* __restrict__ x3)
{
    int gw = (int)(((size_t)blockIdx.x * blockDim.x + threadIdx.x) >> 5);
    if (gw >= 2 * N_TOT) return;
    const int lane = threadIdx.x & 31;
    const int a = (gw >= N_TOT) ? 1 : 0;
    const int r = a ? (gw - N_TOT) : gw;

    int m = g_cnt[a][r];
    if (m > CAP) m = CAP;

    const unsigned long long* rp = g_rec[a] + (size_t)r * CAP;
    unsigned long long rec0 = 0, rec1 = 0;
    if (lane < m)      rec0 = __ldg(rp + lane);
    if (32 + lane < m) rec1 = __ldg(rp + 32 + lane);

    float4 acc = make_float4(0.f, 0.f, 0.f, 0.f);

    int k = 0;
    while (k < m) {
        int batch = m - k; if (batch > 8) batch = 8;
        float4 p[8]; float v[8];
#pragma unroll
        for (int i = 0; i < 8; i++) {
            if (i < batch) {
                int kk = k + i;
                unsigned long long q = (kk < 32)
                    ? __shfl_sync(0xffffffffu, rec0, kk)
                    : __shfl_sync(0xffffffffu, rec1, kk - 32);
                int c = (int)(unsigned)(q & 0xffffffffu);
                v[i] = __uint_as_float((unsigned)(q >> 32));
                p[i] = __ldg((const float4*)(x1 + (size_t)c * NDIM) + lane);
            }
        }
#pragma unroll
        for (int i = 0; i < 8; i++) {
            if (i < batch) {
                acc.x = fmaf(v[i], p[i].x, acc.x);
                acc.y = fmaf(v[i], p[i].y, acc.y);
                acc.z = fmaf(v[i], p[i].z, acc.z);
                acc.w = fmaf(v[i], p[i].w, acc.w);
            }
        }
        k += batch;
    }

    float* out = (a ? x3 : x2) + (size_t)r * NDIM;
    ((float4*)out)[lane] = acc;
}

// ---------------------------------------------------------------------------
// Apply spilled edges (normally zero of them)
// ---------------------------------------------------------------------------
__global__ __launch_bounds__(256) void spill_kernel(
    const float* __restrict__ x1, float* __restrict__ x2, float* __restrict__ x3)
{
    int nspill = g_spill_cnt;
    if (nspill > SPILL_MAX) nspill = SPILL_MAX;
    int lane = threadIdx.x & 31;
    int warp = (blockIdx.x * blockDim.x + threadIdx.x) >> 5;
    int nwarps = (gridDim.x * blockDim.x) >> 5;
    for (int s = warp; s < nspill; s += nwarps) {
        int4 e = g_spill[s];
        int a = (e.x >> 30) & 1;
        int r = e.x & 0x3fffffff;
        float v = __uint_as_float((unsigned)e.z);
        float4 p = __ldg((const float4*)(x1 + (size_t)e.y * NDIM) + lane);
        float* dst = (a ? x3 : x2) + (size_t)r * NDIM + lane * 4;
        asm volatile("red.global.add.v4.f32 [%0], {%1, %2, %3, %4};"
                     :: "l"(dst), "f"(p.x * v), "f"(p.y * v), "f"(p.z * v), "f"(p.w * v)
                     : "memory");
    }
}

// ---------------------------------------------------------------------------
// SIMT fp32 GEMM (known-good)
// ---------------------------------------------------------------------------
__global__ __launch_bounds__(256) void gemm_kernel(
    const float* __restrict__ A0, const float* __restrict__ A1,
    const float* __restrict__ W, float* __restrict__ C)
{
    __shared__ float As[16][128 + 4];
    __shared__ float Ws[16][128 + 4];

    const int t  = threadIdx.x;
    const int tx = t & 15;
    const int ty = t >> 4;
    const int blockRow = blockIdx.x * 128;

    float acc[8][8];
#pragma unroll
    for (int i = 0; i < 8; i++)
#pragma unroll
        for (int j = 0; j < 8; j++) acc[i][j] = 0.f;

    for (int kk = 0; kk < NFEAT; kk += 16) {
#pragma unroll
        for (int l = 0; l < 2; l++) {
            int idx = t + l * 256;
            int r   = idx >> 2;
            int kq  = (idx & 3) << 2;

            int grow = blockRow + r;
            float4 v = make_float4(0.f, 0.f, 0.f, 0.f);
            if (grow < N_TOT) {
                const float* src = (grow < N_NODE)
                    ? (A0 + (size_t)grow * NFEAT)
                    : (A1 + (size_t)(grow - N_NODE) * NFEAT);
                v = *(const float4*)(src + kk + kq);
            }
            As[kq + 0][r] = v.x; As[kq + 1][r] = v.y;
            As[kq + 2][r] = v.z; As[kq + 3][r] = v.w;

            float4 w = *(const float4*)(W + (size_t)r * NFEAT + kk + kq);
            Ws[kq + 0][r] = w.x; Ws[kq + 1][r] = w.y;
            Ws[kq + 2][r] = w.z; Ws[kq + 3][r] = w.w;
        }
        __syncthreads();

#pragma unroll
        for (int k = 0; k < 16; k++) {
            float a[8], b[8];
#pragma unroll
            for (int i = 0; i < 4; i++) {
                a[i]     = As[k][ty * 4 + i];
                a[i + 4] = As[k][64 + ty * 4 + i];
                b[i]     = Ws[k][tx * 4 + i];
                b[i + 4] = Ws[k][64 + tx * 4 + i];
            }
#pragma unroll
            for (int i = 0; i < 8; i++)
#pragma unroll
                for (int j = 0; j < 8; j++)
                    acc[i][j] = fmaf(a[i], b[j], acc[i][j]);
        }
        __syncthreads();
    }

#pragma unroll
    for (int i = 0; i < 8; i++) {
        int rloc = (i < 4) ? (ty * 4 + i) : (64 + ty * 4 + (i - 4));
        int r = blockRow + rloc;
        if (r < N_TOT) {
            float* crow = C + (size_t)r * NDIM;
#pragma unroll
            for (int j = 0; j < 8; j++) {
                int cloc = (j < 4) ? (tx * 4 + j) : (64 + tx * 4 + (j - 4));
                crow[cloc] = acc[i][j];
            }
        }
    }
}

// ---------------------------------------------------------------------------
extern "C" void kernel_launch(void* const* d_in, const int* in_sizes, int n_in,
                              void* d_out, int out_size)
{
    const float* emb_node  = (const float*)d_in[0];
    const float* emb_attri = (const float*)d_in[1];
    const float* W1        = (const float*)d_in[2];
    const int*   adj_row   = (const int*)d_in[3];
    const int*   adj_col   = (const int*)d_in[4];
    const float* adj_val   = (const float*)d_in[5];
    const int*   adj2_row  = (const int*)d_in[6];
    const int*   adj2_col  = (const int*)d_in[7];
    const float* adj2_val  = (const float*)d_in[8];

    float* out = (float*)d_out;
    float* x1 = out;
    float* x2 = out + (size_t)N_TOT * NDIM;
    float* x3 = x2  + (size_t)N_TOT * NDIM;

    const int E = in_sizes[3];

    zero_cnt_kernel<<<208, 256>>>();

    int perAdj = (E + 7) / 8;
    int pblocks = (2 * perAdj + 255) / 256;
    place_kernel<<<pblocks, 256>>>(adj_row,  adj_col,  adj_val,
                                   adj2_row, adj2_col, adj2_val, E, perAdj);

    gemm_kernel<<<(N_TOT + 127) / 128, 256>>>(emb_node, emb_attri, W1, x1);

    long long threads = (long long)2 * N_TOT * 32;
    int sblocks = (int)((threads + 255) / 256);
    spmm_kernel<<<sblocks, 256>>>(x1, x2, x3);

    spill_kernel<<<8, 256>>>(x1, x2, x3);
}

// round 6
// speedup vs baseline: 1.5306x; 1.5306x over previous
#include <cuda_runtime.h>
#include <cstdint>

#define N_NODE 100000
#define N_TOT  102000
#define NFEAT  256
#define NDIM   128
#define CAP    64
#define SPILL_MAX 8192

typedef unsigned long long u64;

// ---------------------------------------------------------------------------
// Device scratch: ELL bins for both adjacencies + spill safety net
// ---------------------------------------------------------------------------
__device__ int  g_cnt[2][N_TOT];
__device__ u64  g_rec[2][(size_t)N_TOT * CAP];
__device__ int  g_spill_cnt;
__device__ int4 g_spill[SPILL_MAX];   // {row | a<<30, col, valbits, -}

// ---------------------------------------------------------------------------
__global__ void zero_cnt_kernel() {
    int i = blockIdx.x * blockDim.x + threadIdx.x;
    int n = 2 * N_TOT;
    int stride = gridDim.x * blockDim.x;
    for (int j = i; j < n; j += stride)
        ((int*)g_cnt)[j] = 0;
    if (i == 0) g_spill_cnt = 0;
}

// ---------------------------------------------------------------------------
// ELL placement: one pass, 8 edges/thread, both adjacencies
// ---------------------------------------------------------------------------
__global__ __launch_bounds__(256) void place_kernel(
    const int* __restrict__ erow1, const int* __restrict__ ecol1, const float* __restrict__ eval1,
    const int* __restrict__ erow2, const int* __restrict__ ecol2, const float* __restrict__ eval2,
    int E, int perAdj)
{
    int idx = blockIdx.x * blockDim.x + threadIdx.x;
    int a = 0;
    if (idx >= perAdj) { a = 1; idx -= perAdj; if (idx >= perAdj) return; }
    const int*   erow = a ? erow2 : erow1;
    const int*   ecol = a ? ecol2 : ecol1;
    const float* eval = a ? eval2 : eval1;
    u64* rec = g_rec[a];
    int* cnt = g_cnt[a];

    int e0 = idx * 8;
    int nn = (e0 + 8 <= E) ? 8 : (E - e0);
    if (nn <= 0) return;

    int rr[8], cc[8]; float vv[8];
#pragma unroll
    for (int q = 0; q < 2; q++) {
        if (e0 + q * 4 + 4 <= E) {
            int4   r4 = *(const int4*)(erow + e0 + q * 4);
            int4   c4 = *(const int4*)(ecol + e0 + q * 4);
            float4 v4 = *(const float4*)(eval + e0 + q * 4);
            rr[q*4+0] = r4.x; rr[q*4+1] = r4.y; rr[q*4+2] = r4.z; rr[q*4+3] = r4.w;
            cc[q*4+0] = c4.x; cc[q*4+1] = c4.y; cc[q*4+2] = c4.z; cc[q*4+3] = c4.w;
            vv[q*4+0] = v4.x; vv[q*4+1] = v4.y; vv[q*4+2] = v4.z; vv[q*4+3] = v4.w;
        } else {
            for (int i = q * 4; i < nn; i++) {
                rr[i] = __ldg(erow + e0 + i);
                cc[i] = __ldg(ecol + e0 + i);
                vv[i] = __ldg(eval + e0 + i);
            }
        }
    }

    int pos[8];
#pragma unroll
    for (int i = 0; i < 8; i++)
        if (i < nn) pos[i] = atomicAdd(&cnt[rr[i]], 1);

#pragma unroll
    for (int i = 0; i < 8; i++) {
        if (i < nn) {
            u64 r8 = (u64)(unsigned)cc[i]
                   | ((u64)__float_as_uint(vv[i]) << 32);
            if (pos[i] < CAP) {
                rec[(size_t)rr[i] * CAP + pos[i]] = r8;
            } else {
                int s = atomicAdd(&g_spill_cnt, 1);
                if (s < SPILL_MAX)
                    g_spill[s] = make_int4(rr[i] | (a << 30), cc[i],
                                           (int)__float_as_uint(vv[i]), 0);
            }
        }
    }
}

// ---------------------------------------------------------------------------
// SpMM v3: grid-stride warps, 1 row per warp iteration.
// Records: ONE coalesced lane-parallel load per row, broadcast via shfl.
// Gathers: batches of 4 (p[4] live only -> low registers).
// ---------------------------------------------------------------------------
__global__ __launch_bounds__(256) void spmm_kernel(
    const float* __restrict__ x1, float* __restrict__ x2, float* __restrict__ x3)
{
    const int lane  = threadIdx.x & 31;
    const int warp0 = (int)(((size_t)blockIdx.x * blockDim.x + threadIdx.x) >> 5);
    const int nw    = (gridDim.x * blockDim.x) >> 5;

    for (int gw = warp0; gw < 2 * N_TOT; gw += nw) {
        const int a = (gw >= N_TOT) ? 1 : 0;
        const int r = a ? (gw - N_TOT) : gw;

        int m = g_cnt[a][r];
        if (m > CAP) m = CAP;
        const u64* rp = g_rec[a] + (size_t)r * CAP;

        u64 myrec = 0;
        if (lane < m) myrec = __ldg(rp + lane);

        float4 acc = make_float4(0.f, 0.f, 0.f, 0.f);
        const int m1 = (m < 32) ? m : 32;
        int k = 0;

        for (; k + 4 <= m1; k += 4) {
            u64 q0 = __shfl_sync(0xffffffffu, myrec, k);
            u64 q1 = __shfl_sync(0xffffffffu, myrec, k + 1);
            u64 q2 = __shfl_sync(0xffffffffu, myrec, k + 2);
            u64 q3 = __shfl_sync(0xffffffffu, myrec, k + 3);
            float4 p0 = __ldg((const float4*)(x1 + (size_t)(unsigned)q0 * NDIM) + lane);
            float4 p1 = __ldg((const float4*)(x1 + (size_t)(unsigned)q1 * NDIM) + lane);
            float4 p2 = __ldg((const float4*)(x1 + (size_t)(unsigned)q2 * NDIM) + lane);
            float4 p3 = __ldg((const float4*)(x1 + (size_t)(unsigned)q3 * NDIM) + lane);
            float v0 = __uint_as_float((unsigned)(q0 >> 32));
            float v1 = __uint_as_float((unsigned)(q1 >> 32));
            float v2 = __uint_as_float((unsigned)(q2 >> 32));
            float v3 = __uint_as_float((unsigned)(q3 >> 32));
            acc.x = fmaf(v0, p0.x, acc.x); acc.y = fmaf(v0, p0.y, acc.y);
            acc.z = fmaf(v0, p0.z, acc.z); acc.w = fmaf(v0, p0.w, acc.w);
            acc.x = fmaf(v1, p1.x, acc.x); acc.y = fmaf(v1, p1.y, acc.y);
            acc.z = fmaf(v1, p1.z, acc.z); acc.w = fmaf(v1, p1.w, acc.w);
            acc.x = fmaf(v2, p2.x, acc.x); acc.y = fmaf(v2, p2.y, acc.y);
            acc.z = fmaf(v2, p2.z, acc.z); acc.w = fmaf(v2, p2.w, acc.w);
            acc.x = fmaf(v3, p3.x, acc.x); acc.y = fmaf(v3, p3.y, acc.y);
            acc.z = fmaf(v3, p3.z, acc.z); acc.w = fmaf(v3, p3.w, acc.w);
        }
        for (; k < m1; k++) {
            u64 q = __shfl_sync(0xffffffffu, myrec, k);
            float4 p = __ldg((const float4*)(x1 + (size_t)(unsigned)q * NDIM) + lane);
            float v = __uint_as_float((unsigned)(q >> 32));
            acc.x = fmaf(v, p.x, acc.x); acc.y = fmaf(v, p.y, acc.y);
            acc.z = fmaf(v, p.z, acc.z); acc.w = fmaf(v, p.w, acc.w);
        }
        for (; k < m; k++) {          // rare: degree > 32
            u64 q = __ldg(rp + k);
            float4 p = __ldg((const float4*)(x1 + (size_t)(unsigned)q * NDIM) + lane);
            float v = __uint_as_float((unsigned)(q >> 32));
            acc.x = fmaf(v, p.x, acc.x); acc.y = fmaf(v, p.y, acc.y);
            acc.z = fmaf(v, p.z, acc.z); acc.w = fmaf(v, p.w, acc.w);
        }

        float* outp = (a ? x3 : x2) + (size_t)r * NDIM;
        ((float4*)outp)[lane] = acc;
    }
}

// ---------------------------------------------------------------------------
// Apply spilled edges (normally zero of them)
// ---------------------------------------------------------------------------
__global__ __launch_bounds__(256) void spill_kernel(
    const float* __restrict__ x1, float* __restrict__ x2, float* __restrict__ x3)
{
    int nspill = g_spill_cnt;
    if (nspill > SPILL_MAX) nspill = SPILL_MAX;
    int lane = threadIdx.x & 31;
    int warp = (blockIdx.x * blockDim.x + threadIdx.x) >> 5;
    int nwarps = (gridDim.x * blockDim.x) >> 5;
    for (int s = warp; s < nspill; s += nwarps) {
        int4 e = g_spill[s];
        int a = (e.x >> 30) & 1;
        int r = e.x & 0x3fffffff;
        float v = __uint_as_float((unsigned)e.z);
        float4 p = __ldg((const float4*)(x1 + (size_t)e.y * NDIM) + lane);
        float* dst = (a ? x3 : x2) + (size_t)r * NDIM + lane * 4;
        asm volatile("red.global.add.v4.f32 [%0], {%1, %2, %3, %4};"
                     :: "l"(dst), "f"(p.x * v), "f"(p.y * v), "f"(p.z * v), "f"(p.w * v)
                     : "memory");
    }
}

// ---------------------------------------------------------------------------
// SIMT fp32 GEMM (known-good, unchanged)
// ---------------------------------------------------------------------------
__global__ __launch_bounds__(256) void gemm_kernel(
    const float* __restrict__ A0, const float* __restrict__ A1,
    const float* __restrict__ W, float* __restrict__ C)
{
    __shared__ float As[16][128 + 4];
    __shared__ float Ws[16][128 + 4];

    const int t  = threadIdx.x;
    const int tx = t & 15;
    const int ty = t >> 4;
    const int blockRow = blockIdx.x * 128;

    float acc[8][8];
#pragma unroll
    for (int i = 0; i < 8; i++)
#pragma unroll
        for (int j = 0; j < 8; j++) acc[i][j] = 0.f;

    for (int kk = 0; kk < NFEAT; kk += 16) {
#pragma unroll
        for (int l = 0; l < 2; l++) {
            int idx = t + l * 256;
            int r   = idx >> 2;
            int kq  = (idx & 3) << 2;

            int grow = blockRow + r;
            float4 v = make_float4(0.f, 0.f, 0.f, 0.f);
            if (grow < N_TOT) {
                const float* src = (grow < N_NODE)
                    ? (A0 + (size_t)grow * NFEAT)
                    : (A1 + (size_t)(grow - N_NODE) * NFEAT);
                v = *(const float4*)(src + kk + kq);
            }
            As[kq + 0][r] = v.x; As[kq + 1][r] = v.y;
            As[kq + 2][r] = v.z; As[kq + 3][r] = v.w;

            float4 w = *(const float4*)(W + (size_t)r * NFEAT + kk + kq);
            Ws[kq + 0][r] = w.x; Ws[kq + 1][r] = w.y;
            Ws[kq + 2][r] = w.z; Ws[kq + 3][r] = w.w;
        }
        __syncthreads();

#pragma unroll
        for (int k = 0; k < 16; k++) {
            float a[8], b[8];
#pragma unroll
            for (int i = 0; i < 4; i++) {
                a[i]     = As[k][ty * 4 + i];
                a[i + 4] = As[k][64 + ty * 4 + i];
                b[i]     = Ws[k][tx * 4 + i];
                b[i + 4] = Ws[k][64 + tx * 4 + i];
            }
#pragma unroll
            for (int i = 0; i < 8; i++)
#pragma unroll
                for (int j = 0; j < 8; j++)
                    acc[i][j] = fmaf(a[i], b[j], acc[i][j]);
        }
        __syncthreads();
    }

#pragma unroll
    for (int i = 0; i < 8; i++) {
        int rloc = (i < 4) ? (ty * 4 + i) : (64 + ty * 4 + (i - 4));
        int r = blockRow + rloc;
        if (r < N_TOT) {
            float* crow = C + (size_t)r * NDIM;
#pragma unroll
            for (int j = 0; j < 8; j++) {
                int cloc = (j < 4) ? (tx * 4 + j) : (64 + tx * 4 + (j - 4));
                crow[cloc] = acc[i][j];
            }
        }
    }
}

// ---------------------------------------------------------------------------
extern "C" void kernel_launch(void* const* d_in, const int* in_sizes, int n_in,
                              void* d_out, int out_size)
{
    const float* emb_node  = (const float*)d_in[0];
    const float* emb_attri = (const float*)d_in[1];
    const float* W1        = (const float*)d_in[2];
    const int*   adj_row   = (const int*)d_in[3];
    const int*   adj_col   = (const int*)d_in[4];
    const float* adj_val   = (const float*)d_in[5];
    const int*   adj2_row  = (const int*)d_in[6];
    const int*   adj2_col  = (const int*)d_in[7];
    const float* adj2_val  = (const float*)d_in[8];

    float* out = (float*)d_out;
    float* x1 = out;
    float* x2 = out + (size_t)N_TOT * NDIM;
    float* x3 = x2  + (size_t)N_TOT * NDIM;

    const int E = in_sizes[3];

    zero_cnt_kernel<<<208, 256>>>();

    int perAdj = (E + 7) / 8;
    int pblocks = (2 * perAdj + 255) / 256;
    place_kernel<<<pblocks, 256>>>(adj_row,  adj_col,  adj_val,
                                   adj2_row, adj2_col, adj2_val, E, perAdj);

    gemm_kernel<<<(N_TOT + 127) / 128, 256>>>(emb_node, emb_attri, W1, x1);

    // 4 rows per warp: 2*N_TOT / 4 warps = 51000 warps = 6375 blocks
    spmm_kernel<<<6375, 256>>>(x1, x2, x3);

    spill_kernel<<<8, 256>>>(x1, x2, x3);
}

// round 8
// speedup vs baseline: 1.6514x; 1.0790x over previous
#include <cuda_runtime.h>
#include <cuda_bf16.h>
#include <cstdint>

#define N_NODE 100000
#define N_TOT  102000
#define NFEAT  256
#define NDIM   128
#define CAP    64
#define SPILL_MAX 8192

typedef unsigned long long u64;

// ===========================================================================
// Device scratch: ELL bins + spill (unchanged from R6 winner)
// ===========================================================================
__device__ int  g_cnt[2][N_TOT];
__device__ u64  g_rec[2][(size_t)N_TOT * CAP];
__device__ int  g_spill_cnt;
__device__ int4 g_spill[SPILL_MAX];

__global__ void zero_cnt_kernel() {
    int i = blockIdx.x * blockDim.x + threadIdx.x;
    int n = 2 * N_TOT;
    int stride = gridDim.x * blockDim.x;
    for (int j = i; j < n; j += stride)
        ((int*)g_cnt)[j] = 0;
    if (i == 0) g_spill_cnt = 0;
}

__global__ __launch_bounds__(256) void place_kernel(
    const int* __restrict__ erow1, const int* __restrict__ ecol1, const float* __restrict__ eval1,
    const int* __restrict__ erow2, const int* __restrict__ ecol2, const float* __restrict__ eval2,
    int E, int perAdj)
{
    int idx = blockIdx.x * blockDim.x + threadIdx.x;
    int a = 0;
    if (idx >= perAdj) { a = 1; idx -= perAdj; if (idx >= perAdj) return; }
    const int*   erow = a ? erow2 : erow1;
    const int*   ecol = a ? ecol2 : ecol1;
    const float* eval = a ? eval2 : eval1;
    u64* rec = g_rec[a];
    int* cnt = g_cnt[a];

    int e0 = idx * 8;
    int nn = (e0 + 8 <= E) ? 8 : (E - e0);
    if (nn <= 0) return;

    int rr[8], cc[8]; float vv[8];
#pragma unroll
    for (int q = 0; q < 2; q++) {
        if (e0 + q * 4 + 4 <= E) {
            int4   r4 = *(const int4*)(erow + e0 + q * 4);
            int4   c4 = *(const int4*)(ecol + e0 + q * 4);
            float4 v4 = *(const float4*)(eval + e0 + q * 4);
            rr[q*4+0] = r4.x; rr[q*4+1] = r4.y; rr[q*4+2] = r4.z; rr[q*4+3] = r4.w;
            cc[q*4+0] = c4.x; cc[q*4+1] = c4.y; cc[q*4+2] = c4.z; cc[q*4+3] = c4.w;
            vv[q*4+0] = v4.x; vv[q*4+1] = v4.y; vv[q*4+2] = v4.z; vv[q*4+3] = v4.w;
        } else {
            for (int i = q * 4; i < nn; i++) {
                rr[i] = __ldg(erow + e0 + i);
                cc[i] = __ldg(ecol + e0 + i);
                vv[i] = __ldg(eval + e0 + i);
            }
        }
    }

    int pos[8];
#pragma unroll
    for (int i = 0; i < 8; i++)
        if (i < nn) pos[i] = atomicAdd(&cnt[rr[i]], 1);

#pragma unroll
    for (int i = 0; i < 8; i++) {
        if (i < nn) {
            u64 r8 = (u64)(unsigned)cc[i] | ((u64)__float_as_uint(vv[i]) << 32);
            if (pos[i] < CAP) {
                rec[(size_t)rr[i] * CAP + pos[i]] = r8;
            } else {
                int s = atomicAdd(&g_spill_cnt, 1);
                if (s < SPILL_MAX)
                    g_spill[s] = make_int4(rr[i] | (a << 30), cc[i],
                                           (int)__float_as_uint(vv[i]), 0);
            }
        }
    }
}

// ---------------------------------------------------------------------------
// SpMM v3 (unchanged from R6 winner)
// ---------------------------------------------------------------------------
__global__ __launch_bounds__(256) void spmm_kernel(
    const float* __restrict__ x1, float* __restrict__ x2, float* __restrict__ x3)
{
    const int lane  = threadIdx.x & 31;
    const int warp0 = (int)(((size_t)blockIdx.x * blockDim.x + threadIdx.x) >> 5);
    const int nw    = (gridDim.x * blockDim.x) >> 5;

    for (int gw = warp0; gw < 2 * N_TOT; gw += nw) {
        const int a = (gw >= N_TOT) ? 1 : 0;
        const int r = a ? (gw - N_TOT) : gw;

        int m = g_cnt[a][r];
        if (m > CAP) m = CAP;
        const u64* rp = g_rec[a] + (size_t)r * CAP;

        u64 myrec = 0;
        if (lane < m) myrec = __ldg(rp + lane);

        float4 acc = make_float4(0.f, 0.f, 0.f, 0.f);
        const int m1 = (m < 32) ? m : 32;
        int k = 0;

        for (; k + 4 <= m1; k += 4) {
            u64 q0 = __shfl_sync(0xffffffffu, myrec, k);
            u64 q1 = __shfl_sync(0xffffffffu, myrec, k + 1);
            u64 q2 = __shfl_sync(0xffffffffu, myrec, k + 2);
            u64 q3 = __shfl_sync(0xffffffffu, myrec, k + 3);
            float4 p0 = __ldg((const float4*)(x1 + (size_t)(unsigned)q0 * NDIM) + lane);
            float4 p1 = __ldg((const float4*)(x1 + (size_t)(unsigned)q1 * NDIM) + lane);
            float4 p2 = __ldg((const float4*)(x1 + (size_t)(unsigned)q2 * NDIM) + lane);
            float4 p3 = __ldg((const float4*)(x1 + (size_t)(unsigned)q3 * NDIM) + lane);
            float v0 = __uint_as_float((unsigned)(q0 >> 32));
            float v1 = __uint_as_float((unsigned)(q1 >> 32));
            float v2 = __uint_as_float((unsigned)(q2 >> 32));
            float v3 = __uint_as_float((unsigned)(q3 >> 32));
            acc.x = fmaf(v0, p0.x, acc.x); acc.y = fmaf(v0, p0.y, acc.y);
            acc.z = fmaf(v0, p0.z, acc.z); acc.w = fmaf(v0, p0.w, acc.w);
            acc.x = fmaf(v1, p1.x, acc.x); acc.y = fmaf(v1, p1.y, acc.y);
            acc.z = fmaf(v1, p1.z, acc.z); acc.w = fmaf(v1, p1.w, acc.w);
            acc.x = fmaf(v2, p2.x, acc.x); acc.y = fmaf(v2, p2.y, acc.y);
            acc.z = fmaf(v2, p2.z, acc.z); acc.w = fmaf(v2, p2.w, acc.w);
            acc.x = fmaf(v3, p3.x, acc.x); acc.y = fmaf(v3, p3.y, acc.y);
            acc.z = fmaf(v3, p3.z, acc.z); acc.w = fmaf(v3, p3.w, acc.w);
        }
        for (; k < m1; k++) {
            u64 q = __shfl_sync(0xffffffffu, myrec, k);
            float4 p = __ldg((const float4*)(x1 + (size_t)(unsigned)q * NDIM) + lane);
            float v = __uint_as_float((unsigned)(q >> 32));
            acc.x = fmaf(v, p.x, acc.x); acc.y = fmaf(v, p.y, acc.y);
            acc.z = fmaf(v, p.z, acc.z); acc.w = fmaf(v, p.w, acc.w);
        }
        for (; k < m; k++) {
            u64 q = __ldg(rp + k);
            float4 p = __ldg((const float4*)(x1 + (size_t)(unsigned)q * NDIM) + lane);
            float v = __uint_as_float((unsigned)(q >> 32));
            acc.x = fmaf(v, p.x, acc.x); acc.y = fmaf(v, p.y, acc.y);
            acc.z = fmaf(v, p.z, acc.z); acc.w = fmaf(v, p.w, acc.w);
        }

        float* outp = (a ? x3 : x2) + (size_t)r * NDIM;
        ((float4*)outp)[lane] = acc;
    }
}

__global__ __launch_bounds__(256) void spill_kernel(
    const float* __restrict__ x1, float* __restrict__ x2, float* __restrict__ x3)
{
    int nspill = g_spill_cnt;
    if (nspill > SPILL_MAX) nspill = SPILL_MAX;
    int lane = threadIdx.x & 31;
    int warp = (blockIdx.x * blockDim.x + threadIdx.x) >> 5;
    int nwarps = (gridDim.x * blockDim.x) >> 5;
    for (int s = warp; s < nspill; s += nwarps) {
        int4 e = g_spill[s];
        int a = (e.x >> 30) & 1;
        int r = e.x & 0x3fffffff;
        float v = __uint_as_float((unsigned)e.z);
        float4 p = __ldg((const float4*)(x1 + (size_t)e.y * NDIM) + lane);
        float* dst = (a ? x3 : x2) + (size_t)r * NDIM + lane * 4;
        asm volatile("red.global.add.v4.f32 [%0], {%1, %2, %3, %4};"
                     :: "l"(dst), "f"(p.x * v), "f"(p.y * v), "f"(p.z * v), "f"(p.w * v)
                     : "memory");
    }
}

// ===========================================================================
// bf16-split warp-MMA GEMM: C = concat(A0,A1) @ W^T, fp32 accum.
// D += Ahi*Whi + Ahi*Wlo + Alo*Whi  (lo*lo dropped, ~2^-16 rel).
// BM=128, BN=128, BK=32. 256 threads = 8 warps (4M x 2N), warp tile 32x64.
// smem: bf16 tiles, 64B rows (32 bf16), 16B-chunk XOR swizzle; ldmatrix.x4.
// ===========================================================================
__device__ __forceinline__ uint32_t smem_u32(const void* p) {
    uint32_t a;
    asm("{ .reg .u64 t; cvta.to.shared.u64 t, %1; cvt.u32.u64 %0, t; }"
        : "=r"(a) : "l"(p));
    return a;
}
__device__ __forceinline__ void ldmatrix4(uint32_t* r, uint32_t addr) {
    asm volatile("ldmatrix.sync.aligned.m8n8.x4.shared.b16 {%0,%1,%2,%3}, [%4];"
                 : "=r"(r[0]), "=r"(r[1]), "=r"(r[2]), "=r"(r[3]) : "r"(addr));
}
__device__ __forceinline__ void mma_bf16(float* d, const uint32_t* a,
                                         uint32_t b0, uint32_t b1) {
    asm volatile("mma.sync.aligned.m16n8k16.row.col.f32.bf16.bf16.f32 "
                 "{%0,%1,%2,%3},{%4,%5,%6,%7},{%8,%9},{%0,%1,%2,%3};"
                 : "+f"(d[0]), "+f"(d[1]), "+f"(d[2]), "+f"(d[3])
                 : "r"(a[0]), "r"(a[1]), "r"(a[2]), "r"(a[3]), "r"(b0), "r"(b1));
}

// pack 16 fp32 -> 8 bf16x2 hi + 8 bf16x2 lo
__device__ __forceinline__ void split_pack(const float4* v, uint32_t* hp, uint32_t* lp) {
    const float* f = (const float*)v;
#pragma unroll
    for (int i = 0; i < 8; i++) {
        __nv_bfloat16 h0 = __float2bfloat16(f[2*i]);
        __nv_bfloat16 h1 = __float2bfloat16(f[2*i+1]);
        __nv_bfloat16 l0 = __float2bfloat16(f[2*i]   - __bfloat162float(h0));
        __nv_bfloat16 l1 = __float2bfloat16(f[2*i+1] - __bfloat162float(h1));
        hp[i] = (uint32_t)__bfloat16_as_ushort(h0) | ((uint32_t)__bfloat16_as_ushort(h1) << 16);
        lp[i] = (uint32_t)__bfloat16_as_ushort(l0) | ((uint32_t)__bfloat16_as_ushort(l1) << 16);
    }
}
// store 16 elements (row, k-half) into swizzled tile: 2 x 16B chunks
__device__ __forceinline__ void store_tile(uint16_t* hiB, uint16_t* loB,
                                           int row, int half,
                                           const uint32_t* hp, const uint32_t* lp) {
    char* hc = (char*)hiB + row * 64;
    char* lc = (char*)loB + row * 64;
    int sw = row & 3;
#pragma unroll
    for (int cc = 0; cc < 2; cc++) {
        int ch = (half * 2 + cc) ^ sw;
        *(uint4*)(hc + ch * 16) = make_uint4(hp[cc*4], hp[cc*4+1], hp[cc*4+2], hp[cc*4+3]);
        *(uint4*)(lc + ch * 16) = make_uint4(lp[cc*4], lp[cc*4+1], lp[cc*4+2], lp[cc*4+3]);
    }
}

__global__ __launch_bounds__(256, 1) void gemm_mma_kernel(
    const float* __restrict__ A0, const float* __restrict__ A1,
    const float* __restrict__ W, float* __restrict__ C)
{
    __shared__ __align__(128) uint16_t sAhi[128 * 32];
    __shared__ __align__(128) uint16_t sAlo[128 * 32];
    __shared__ __align__(128) uint16_t sWhi[128 * 32];
    __shared__ __align__(128) uint16_t sWlo[128 * 32];

    const int t    = threadIdx.x;
    const int lane = t & 31;
    const int wid  = t >> 5;
    const int warpM = (wid & 3) * 32;
    const int warpN = (wid >> 2) * 64;
    const int blockRow = blockIdx.x * 128;

    // loader mapping: 2 threads per row, 16 floats each
    const int lrow  = t >> 1;
    const int lhalf = t & 1;
    const int grow  = blockRow + lrow;
    const float* asrc = nullptr;
    if (grow < N_NODE)      asrc = A0 + (size_t)grow * NFEAT;
    else if (grow < N_TOT)  asrc = A1 + (size_t)(grow - N_NODE) * NFEAT;
    const float* wsrc = W + (size_t)lrow * NFEAT;

    const uint32_t bAhi = smem_u32(sAhi), bAlo = smem_u32(sAlo);
    const uint32_t bWhi = smem_u32(sWhi), bWlo = smem_u32(sWlo);

    // per-lane ldmatrix row/chunk components
    const int l15 = lane & 15;
    const int lk  = lane >> 4;   // which k-half chunk

    float acc[2][8][4];
#pragma unroll
    for (int mt = 0; mt < 2; mt++)
#pragma unroll
        for (int nt = 0; nt < 8; nt++)
#pragma unroll
            for (int i = 0; i < 4; i++) acc[mt][nt][i] = 0.f;

    // prefetch k-tile 0
    float4 pa[4], pw[4];
#pragma unroll
    for (int i = 0; i < 4; i++) {
        pa[i] = asrc ? __ldg((const float4*)(asrc + lhalf * 16) + i)
                     : make_float4(0.f, 0.f, 0.f, 0.f);
        pw[i] = __ldg((const float4*)(wsrc + lhalf * 16) + i);
    }

    for (int ki = 0; ki < 8; ki++) {
        // convert + store current tile
        {
            uint32_t hp[8], lp[8];
            split_pack(pa, hp, lp);
            store_tile(sAhi, sAlo, lrow, lhalf, hp, lp);
            split_pack(pw, hp, lp);
            store_tile(sWhi, sWlo, lrow, lhalf, hp, lp);
        }
        __syncthreads();

        // prefetch next tile while MMAs run
        if (ki < 7) {
            const int kk = (ki + 1) * 32;
#pragma unroll
            for (int i = 0; i < 4; i++) {
                pa[i] = asrc ? __ldg((const float4*)(asrc + kk + lhalf * 16) + i)
                             : make_float4(0.f, 0.f, 0.f, 0.f);
                pw[i] = __ldg((const float4*)(wsrc + kk + lhalf * 16) + i);
            }
        }

#pragma unroll
        for (int ks = 0; ks < 2; ks++) {
            uint32_t ah[2][4], al[2][4];
#pragma unroll
            for (int mt = 0; mt < 2; mt++) {
                int r  = warpM + mt * 16 + l15;
                int ch = ks * 2 + lk;
                uint32_t off = (uint32_t)(r * 64) + (uint32_t)((ch ^ (r & 3)) << 4);
                ldmatrix4(ah[mt], bAhi + off);
                ldmatrix4(al[mt], bAlo + off);
            }
#pragma unroll
            for (int np = 0; np < 4; np++) {
                int rn = warpN + np * 16 + l15;
                int ch = ks * 2 + lk;
                uint32_t off = (uint32_t)(rn * 64) + (uint32_t)((ch ^ (rn & 3)) << 4);
                uint32_t bh[4], bl[4];
                ldmatrix4(bh, bWhi + off);
                ldmatrix4(bl, bWlo + off);
#pragma unroll
                for (int sub = 0; sub < 2; sub++) {
                    uint32_t bh0 = bh[sub], bh1 = bh[sub + 2];
                    uint32_t bl0 = bl[sub], bl1 = bl[sub + 2];
                    int nt = np * 2 + sub;
#pragma unroll
                    for (int mt = 0; mt < 2; mt++) {
                        float* d = acc[mt][nt];
                        mma_bf16(d, al[mt], bh0, bh1);   // lo*hi
                        mma_bf16(d, ah[mt], bl0, bl1);   // hi*lo
                        mma_bf16(d, ah[mt], bh0, bh1);   // hi*hi
                    }
                }
            }
        }
        __syncthreads();
    }

    // epilogue: c0,c1 -> (row, 2c); c2,c3 -> (row+8, 2c)
    const int erow = blockRow + warpM + (lane >> 2);
    const int ecol = (lane & 3) * 2;
#pragma unroll
    for (int mt = 0; mt < 2; mt++) {
        int r0 = erow + mt * 16;
#pragma unroll
        for (int nt = 0; nt < 8; nt++) {
            const float* d = acc[mt][nt];
            int col = warpN + nt * 8 + ecol;
            if (r0 < N_TOT)
                *(float2*)(C + (size_t)r0 * NDIM + col) = make_float2(d[0], d[1]);
            if (r0 + 8 < N_TOT)
                *(float2*)(C + (size_t)(r0 + 8) * NDIM + col) = make_float2(d[2], d[3]);
        }
    }
}

// ===========================================================================
extern "C" void kernel_launch(void* const* d_in, const int* in_sizes, int n_in,
                              void* d_out, int out_size)
{
    const float* emb_node  = (const float*)d_in[0];
    const float* emb_attri = (const float*)d_in[1];
    const float* W1        = (const float*)d_in[2];
    const int*   adj_row   = (const int*)d_in[3];
    const int*   adj_col   = (const int*)d_in[4];
    const float* adj_val   = (const float*)d_in[5];
    const int*   adj2_row  = (const int*)d_in[6];
    const int*   adj2_col  = (const int*)d_in[7];
    const float* adj2_val  = (const float*)d_in[8];

    float* out = (float*)d_out;
    float* x1 = out;
    float* x2 = out + (size_t)N_TOT * NDIM;
    float* x3 = x2  + (size_t)N_TOT * NDIM;

    const int E = in_sizes[3];

    zero_cnt_kernel<<<208, 256>>>();

    int perAdj = (E + 7) / 8;
    int pblocks = (2 * perAdj + 255) / 256;
    place_kernel<<<pblocks, 256>>>(adj_row,  adj_col,  adj_val,
                                   adj2_row, adj2_col, adj2_val, E, perAdj);

    gemm_mma_kernel<<<(N_TOT + 127) / 128, 256>>>(emb_node, emb_attri, W1, x1);

    spmm_kernel<<<6375, 256>>>(x1, x2, x3);

    spill_kernel<<<8, 256>>>(x1, x2, x3);
}

// round 9
// speedup vs baseline: 1.7686x; 1.0710x over previous
#include <cuda_runtime.h>
#include <cuda_bf16.h>
#include <cstdint>

#define N_NODE 100000
#define N_TOT  102000
#define NFEAT  256
#define NDIM   128
#define CAP    64
#define SPILL_MAX 8192

typedef unsigned long long u64;

// ===========================================================================
// Device scratch: ELL bins + spill + prepacked W tiles
// ===========================================================================
__device__ int  g_cnt[2][N_TOT];
__device__ u64  g_rec[2][(size_t)N_TOT * CAP];
__device__ int  g_spill_cnt;
__device__ int4 g_spill[SPILL_MAX];
// W prepacked in smem-tile byte layout: [8 k-tiles][128 rows x 64B], hi and lo
__device__ __align__(16) uint4 g_Whi_pk[4096];   // 64 KB
__device__ __align__(16) uint4 g_Wlo_pk[4096];   // 64 KB

// ---------------------------------------------------------------------------
// pack 16 fp32 -> 8 bf16x2 hi + 8 bf16x2 lo
// ---------------------------------------------------------------------------
__device__ __forceinline__ void split_pack(const float4* v, uint32_t* hp, uint32_t* lp) {
    const float* f = (const float*)v;
#pragma unroll
    for (int i = 0; i < 8; i++) {
        __nv_bfloat16 h0 = __float2bfloat16(f[2*i]);
        __nv_bfloat16 h1 = __float2bfloat16(f[2*i+1]);
        __nv_bfloat16 l0 = __float2bfloat16(f[2*i]   - __bfloat162float(h0));
        __nv_bfloat16 l1 = __float2bfloat16(f[2*i+1] - __bfloat162float(h1));
        hp[i] = (uint32_t)__bfloat16_as_ushort(h0) | ((uint32_t)__bfloat16_as_ushort(h1) << 16);
        lp[i] = (uint32_t)__bfloat16_as_ushort(l0) | ((uint32_t)__bfloat16_as_ushort(l1) << 16);
    }
}

// ---------------------------------------------------------------------------
// zero counters + (block 0) prepack W into tile layout
// ---------------------------------------------------------------------------
__global__ void zero_cnt_kernel(const float* __restrict__ W) {
    int i = blockIdx.x * blockDim.x + threadIdx.x;
    int n = 2 * N_TOT;
    int stride = gridDim.x * blockDim.x;
    for (int j = i; j < n; j += stride)
        ((int*)g_cnt)[j] = 0;
    if (i == 0) g_spill_cnt = 0;

    if (blockIdx.x == 0) {
        const int t = threadIdx.x;       // 256 threads: (row, half)
        const int r = t >> 1;
        const int half = t & 1;
        const float* wrow = W + (size_t)r * NFEAT;
        char* hB = (char*)g_Whi_pk;
        char* lB = (char*)g_Wlo_pk;
        for (int ki = 0; ki < 8; ki++) {
            float4 v[4];
#pragma unroll
            for (int q = 0; q < 4; q++)
                v[q] = __ldg((const float4*)(wrow + ki * 32 + half * 16) + q);
            uint32_t hp[8], lp[8];
            split_pack(v, hp, lp);
            int sw = r & 3;
#pragma unroll
            for (int cc = 0; cc < 2; cc++) {
                int ch = (half * 2 + cc) ^ sw;
                int off = ki * 8192 + r * 64 + ch * 16;
                *(uint4*)(hB + off) = make_uint4(hp[cc*4], hp[cc*4+1], hp[cc*4+2], hp[cc*4+3]);
                *(uint4*)(lB + off) = make_uint4(lp[cc*4], lp[cc*4+1], lp[cc*4+2], lp[cc*4+3]);
            }
        }
    }
}

// ---------------------------------------------------------------------------
// ELL placement (unchanged from R6 winner)
// ---------------------------------------------------------------------------
__global__ __launch_bounds__(256) void place_kernel(
    const int* __restrict__ erow1, const int* __restrict__ ecol1, const float* __restrict__ eval1,
    const int* __restrict__ erow2, const int* __restrict__ ecol2, const float* __restrict__ eval2,
    int E, int perAdj)
{
    int idx = blockIdx.x * blockDim.x + threadIdx.x;
    int a = 0;
    if (idx >= perAdj) { a = 1; idx -= perAdj; if (idx >= perAdj) return; }
    const int*   erow = a ? erow2 : erow1;
    const int*   ecol = a ? ecol2 : ecol1;
    const float* eval = a ? eval2 : eval1;
    u64* rec = g_rec[a];
    int* cnt = g_cnt[a];

    int e0 = idx * 8;
    int nn = (e0 + 8 <= E) ? 8 : (E - e0);
    if (nn <= 0) return;

    int rr[8], cc[8]; float vv[8];
#pragma unroll
    for (int q = 0; q < 2; q++) {
        if (e0 + q * 4 + 4 <= E) {
            int4   r4 = *(const int4*)(erow + e0 + q * 4);
            int4   c4 = *(const int4*)(ecol + e0 + q * 4);
            float4 v4 = *(const float4*)(eval + e0 + q * 4);
            rr[q*4+0] = r4.x; rr[q*4+1] = r4.y; rr[q*4+2] = r4.z; rr[q*4+3] = r4.w;
            cc[q*4+0] = c4.x; cc[q*4+1] = c4.y; cc[q*4+2] = c4.z; cc[q*4+3] = c4.w;
            vv[q*4+0] = v4.x; vv[q*4+1] = v4.y; vv[q*4+2] = v4.z; vv[q*4+3] = v4.w;
        } else {
            for (int i = q * 4; i < nn; i++) {
                rr[i] = __ldg(erow + e0 + i);
                cc[i] = __ldg(ecol + e0 + i);
                vv[i] = __ldg(eval + e0 + i);
            }
        }
    }

    int pos[8];
#pragma unroll
    for (int i = 0; i < 8; i++)
        if (i < nn) pos[i] = atomicAdd(&cnt[rr[i]], 1);

#pragma unroll
    for (int i = 0; i < 8; i++) {
        if (i < nn) {
            u64 r8 = (u64)(unsigned)cc[i] | ((u64)__float_as_uint(vv[i]) << 32);
            if (pos[i] < CAP) {
                rec[(size_t)rr[i] * CAP + pos[i]] = r8;
            } else {
                int s = atomicAdd(&g_spill_cnt, 1);
                if (s < SPILL_MAX)
                    g_spill[s] = make_int4(rr[i] | (a << 30), cc[i],
                                           (int)__float_as_uint(vv[i]), 0);
            }
        }
    }
}

// ---------------------------------------------------------------------------
// SpMM v3 (unchanged from R6 winner)
// ---------------------------------------------------------------------------
__global__ __launch_bounds__(256) void spmm_kernel(
    const float* __restrict__ x1, float* __restrict__ x2, float* __restrict__ x3)
{
    const int lane  = threadIdx.x & 31;
    const int warp0 = (int)(((size_t)blockIdx.x * blockDim.x + threadIdx.x) >> 5);
    const int nw    = (gridDim.x * blockDim.x) >> 5;

    for (int gw = warp0; gw < 2 * N_TOT; gw += nw) {
        const int a = (gw >= N_TOT) ? 1 : 0;
        const int r = a ? (gw - N_TOT) : gw;

        int m = g_cnt[a][r];
        if (m > CAP) m = CAP;
        const u64* rp = g_rec[a] + (size_t)r * CAP;

        u64 myrec = 0;
        if (lane < m) myrec = __ldg(rp + lane);

        float4 acc = make_float4(0.f, 0.f, 0.f, 0.f);
        const int m1 = (m < 32) ? m : 32;
        int k = 0;

        for (; k + 4 <= m1; k += 4) {
            u64 q0 = __shfl_sync(0xffffffffu, myrec, k);
            u64 q1 = __shfl_sync(0xffffffffu, myrec, k + 1);
            u64 q2 = __shfl_sync(0xffffffffu, myrec, k + 2);
            u64 q3 = __shfl_sync(0xffffffffu, myrec, k + 3);
            float4 p0 = __ldg((const float4*)(x1 + (size_t)(unsigned)q0 * NDIM) + lane);
            float4 p1 = __ldg((const float4*)(x1 + (size_t)(unsigned)q1 * NDIM) + lane);
            float4 p2 = __ldg((const float4*)(x1 + (size_t)(unsigned)q2 * NDIM) + lane);
            float4 p3 = __ldg((const float4*)(x1 + (size_t)(unsigned)q3 * NDIM) + lane);
            float v0 = __uint_as_float((unsigned)(q0 >> 32));
            float v1 = __uint_as_float((unsigned)(q1 >> 32));
            float v2 = __uint_as_float((unsigned)(q2 >> 32));
            float v3 = __uint_as_float((unsigned)(q3 >> 32));
            acc.x = fmaf(v0, p0.x, acc.x); acc.y = fmaf(v0, p0.y, acc.y);
            acc.z = fmaf(v0, p0.z, acc.z); acc.w = fmaf(v0, p0.w, acc.w);
            acc.x = fmaf(v1, p1.x, acc.x); acc.y = fmaf(v1, p1.y, acc.y);
            acc.z = fmaf(v1, p1.z, acc.z); acc.w = fmaf(v1, p1.w, acc.w);
            acc.x = fmaf(v2, p2.x, acc.x); acc.y = fmaf(v2, p2.y, acc.y);
            acc.z = fmaf(v2, p2.z, acc.z); acc.w = fmaf(v2, p2.w, acc.w);
            acc.x = fmaf(v3, p3.x, acc.x); acc.y = fmaf(v3, p3.y, acc.y);
            acc.z = fmaf(v3, p3.z, acc.z); acc.w = fmaf(v3, p3.w, acc.w);
        }
        for (; k < m1; k++) {
            u64 q = __shfl_sync(0xffffffffu, myrec, k);
            float4 p = __ldg((const float4*)(x1 + (size_t)(unsigned)q * NDIM) + lane);
            float v = __uint_as_float((unsigned)(q >> 32));
            acc.x = fmaf(v, p.x, acc.x); acc.y = fmaf(v, p.y, acc.y);
            acc.z = fmaf(v, p.z, acc.z); acc.w = fmaf(v, p.w, acc.w);
        }
        for (; k < m; k++) {
            u64 q = __ldg(rp + k);
            float4 p = __ldg((const float4*)(x1 + (size_t)(unsigned)q * NDIM) + lane);
            float v = __uint_as_float((unsigned)(q >> 32));
            acc.x = fmaf(v, p.x, acc.x); acc.y = fmaf(v, p.y, acc.y);
            acc.z = fmaf(v, p.z, acc.z); acc.w = fmaf(v, p.w, acc.w);
        }

        float* outp = (a ? x3 : x2) + (size_t)r * NDIM;
        ((float4*)outp)[lane] = acc;
    }
}

__global__ __launch_bounds__(256) void spill_kernel(
    const float* __restrict__ x1, float* __restrict__ x2, float* __restrict__ x3)
{
    int nspill = g_spill_cnt;
    if (nspill > SPILL_MAX) nspill = SPILL_MAX;
    int lane = threadIdx.x & 31;
    int warp = (blockIdx.x * blockDim.x + threadIdx.x) >> 5;
    int nwarps = (gridDim.x * blockDim.x) >> 5;
    for (int s = warp; s < nspill; s += nwarps) {
        int4 e = g_spill[s];
        int a = (e.x >> 30) & 1;
        int r = e.x & 0x3fffffff;
        float v = __uint_as_float((unsigned)e.z);
        float4 p = __ldg((const float4*)(x1 + (size_t)e.y * NDIM) + lane);
        float* dst = (a ? x3 : x2) + (size_t)r * NDIM + lane * 4;
        asm volatile("red.global.add.v4.f32 [%0], {%1, %2, %3, %4};"
                     :: "l"(dst), "f"(p.x * v), "f"(p.y * v), "f"(p.z * v), "f"(p.w * v)
                     : "memory");
    }
}

// ===========================================================================
// bf16-split warp-MMA GEMM v2: pipelined, W prepacked + resident in smem.
// D += Ahi*Whi + Ahi*Wlo + Alo*Whi.  BM=128, BN=128, BK=32, 8 k-tiles.
// Dynamic smem: W hi (64K) + W lo (64K) + A double buffer (2 x hi+lo x 8K).
// ===========================================================================
__device__ __forceinline__ uint32_t smem_u32(const void* p) {
    uint32_t a;
    asm("{ .reg .u64 t; cvta.to.shared.u64 t, %1; cvt.u32.u64 %0, t; }"
        : "=r"(a) : "l"(p));
    return a;
}
__device__ __forceinline__ void ldmatrix4(uint32_t* r, uint32_t addr) {
    asm volatile("ldmatrix.sync.aligned.m8n8.x4.shared.b16 {%0,%1,%2,%3}, [%4];"
                 : "=r"(r[0]), "=r"(r[1]), "=r"(r[2]), "=r"(r[3]) : "r"(addr));
}
__device__ __forceinline__ void mma_bf16(float* d, const uint32_t* a,
                                         uint32_t b0, uint32_t b1) {
    asm volatile("mma.sync.aligned.m16n8k16.row.col.f32.bf16.bf16.f32 "
                 "{%0,%1,%2,%3},{%4,%5,%6,%7},{%8,%9},{%0,%1,%2,%3};"
                 : "+f"(d[0]), "+f"(d[1]), "+f"(d[2]), "+f"(d[3])
                 : "r"(a[0]), "r"(a[1]), "r"(a[2]), "r"(a[3]), "r"(b0), "r"(b1));
}

#define SM_WHI   0
#define SM_WLO   65536
#define SM_A     131072            // stage s: +s*16384 (hi), +s*16384+8192 (lo)
#define SM_TOTAL 163840            // 160 KB

__global__ __launch_bounds__(256, 1) void gemm_mma_kernel(
    const float* __restrict__ A0, const float* __restrict__ A1,
    float* __restrict__ C)
{
    extern __shared__ __align__(128) char smem[];
    const uint32_t sb = smem_u32(smem);

    const int t    = threadIdx.x;
    const int lane = t & 31;
    const int wid  = t >> 5;
    const int warpM = (wid & 3) * 32;
    const int warpN = (wid >> 2) * 64;
    const int blockRow = blockIdx.x * 128;

    // ---- copy prepacked W into smem (16 uint4 per thread per half) ----
    {
        uint4* dh = (uint4*)(smem + SM_WHI);
        uint4* dl = (uint4*)(smem + SM_WLO);
#pragma unroll
        for (int i = 0; i < 16; i++) {
            dh[t + i * 256] = g_Whi_pk[t + i * 256];
            dl[t + i * 256] = g_Wlo_pk[t + i * 256];
        }
    }

    // loader mapping: 2 threads per row, 16 floats each
    const int lrow  = t >> 1;
    const int lhalf = t & 1;
    const int grow  = blockRow + lrow;
    const float* asrc = nullptr;
    if (grow < N_NODE)      asrc = A0 + (size_t)grow * NFEAT;
    else if (grow < N_TOT)  asrc = A1 + (size_t)(grow - N_NODE) * NFEAT;

    const int l15 = lane & 15;
    const int lk  = lane >> 4;

    float acc[2][8][4];
#pragma unroll
    for (int mt = 0; mt < 2; mt++)
#pragma unroll
        for (int nt = 0; nt < 8; nt++)
#pragma unroll
            for (int i = 0; i < 4; i++) acc[mt][nt][i] = 0.f;

    // ---- prologue: load + convert + store A tile 0 into stage 0 ----
    float4 pa[4];
#pragma unroll
    for (int i = 0; i < 4; i++)
        pa[i] = asrc ? __ldg((const float4*)(asrc + lhalf * 16) + i)
                     : make_float4(0.f, 0.f, 0.f, 0.f);
    {
        uint32_t hp[8], lp[8];
        split_pack(pa, hp, lp);
        char* hB = smem + SM_A;          // stage 0 hi
        char* lB = smem + SM_A + 8192;   // stage 0 lo
        int sw = lrow & 3;
#pragma unroll
        for (int cc = 0; cc < 2; cc++) {
            int ch = (lhalf * 2 + cc) ^ sw;
            *(uint4*)(hB + lrow * 64 + ch * 16) = make_uint4(hp[cc*4], hp[cc*4+1], hp[cc*4+2], hp[cc*4+3]);
            *(uint4*)(lB + lrow * 64 + ch * 16) = make_uint4(lp[cc*4], lp[cc*4+1], lp[cc*4+2], lp[cc*4+3]);
        }
    }
    __syncthreads();

    // ---- main pipeline ----
    for (int ki = 0; ki < 8; ki++) {
        // issue next tile's global loads (overlap with MMA phase)
        if (ki < 7) {
            const int kk = (ki + 1) * 32;
#pragma unroll
            for (int i = 0; i < 4; i++)
                pa[i] = asrc ? __ldg((const float4*)(asrc + kk + lhalf * 16) + i)
                             : make_float4(0.f, 0.f, 0.f, 0.f);
        }

        // MMA phase on stage[ki&1] + W tile ki
        const uint32_t aHi = sb + SM_A + (uint32_t)(ki & 1) * 16384;
        const uint32_t aLo = aHi + 8192;
        const uint32_t wHi = sb + SM_WHI + (uint32_t)ki * 8192;
        const uint32_t wLo = sb + SM_WLO + (uint32_t)ki * 8192;

#pragma unroll
        for (int ks = 0; ks < 2; ks++) {
            uint32_t ah[2][4], al[2][4];
#pragma unroll
            for (int mt = 0; mt < 2; mt++) {
                int r  = warpM + mt * 16 + l15;
                int ch = ks * 2 + lk;
                uint32_t off = (uint32_t)(r * 64) + (uint32_t)((ch ^ (r & 3)) << 4);
                ldmatrix4(ah[mt], aHi + off);
                ldmatrix4(al[mt], aLo + off);
            }
#pragma unroll
            for (int np = 0; np < 4; np++) {
                int rn = warpN + np * 16 + l15;
                int ch = ks * 2 + lk;
                uint32_t off = (uint32_t)(rn * 64) + (uint32_t)((ch ^ (rn & 3)) << 4);
                uint32_t bh[4], bl[4];
                ldmatrix4(bh, wHi + off);
                ldmatrix4(bl, wLo + off);
#pragma unroll
                for (int sub = 0; sub < 2; sub++) {
                    uint32_t bh0 = bh[sub], bh1 = bh[sub + 2];
                    uint32_t bl0 = bl[sub], bl1 = bl[sub + 2];
                    int nt = np * 2 + sub;
#pragma unroll
                    for (int mt = 0; mt < 2; mt++) {
                        float* d = acc[mt][nt];
                        mma_bf16(d, al[mt], bh0, bh1);
                        mma_bf16(d, ah[mt], bl0, bl1);
                        mma_bf16(d, ah[mt], bh0, bh1);
                    }
                }
            }
        }

        // convert + store next A tile into the other stage
        if (ki < 7) {
            uint32_t hp[8], lp[8];
            split_pack(pa, hp, lp);
            char* hB = smem + SM_A + ((ki + 1) & 1) * 16384;
            char* lB = hB + 8192;
            int sw = lrow & 3;
#pragma unroll
            for (int cc = 0; cc < 2; cc++) {
                int ch = (lhalf * 2 + cc) ^ sw;
                *(uint4*)(hB + lrow * 64 + ch * 16) = make_uint4(hp[cc*4], hp[cc*4+1], hp[cc*4+2], hp[cc*4+3]);
                *(uint4*)(lB + lrow * 64 + ch * 16) = make_uint4(lp[cc*4], lp[cc*4+1], lp[cc*4+2], lp[cc*4+3]);
            }
        }
        __syncthreads();
    }

    // ---- epilogue ----
    const int erow = blockRow + warpM + (lane >> 2);
    const int ecol = (lane & 3) * 2;
#pragma unroll
    for (int mt = 0; mt < 2; mt++) {
        int r0 = erow + mt * 16;
#pragma unroll
        for (int nt = 0; nt < 8; nt++) {
            const float* d = acc[mt][nt];
            int col = warpN + nt * 8 + ecol;
            if (r0 < N_TOT)
                *(float2*)(C + (size_t)r0 * NDIM + col) = make_float2(d[0], d[1]);
            if (r0 + 8 < N_TOT)
                *(float2*)(C + (size_t)(r0 + 8) * NDIM + col) = make_float2(d[2], d[3]);
        }
    }
}

// ===========================================================================
extern "C" void kernel_launch(void* const* d_in, const int* in_sizes, int n_in,
                              void* d_out, int out_size)
{
    const float* emb_node  = (const float*)d_in[0];
    const float* emb_attri = (const float*)d_in[1];
    const float* W1        = (const float*)d_in[2];
    const int*   adj_row   = (const int*)d_in[3];
    const int*   adj_col   = (const int*)d_in[4];
    const float* adj_val   = (const float*)d_in[5];
    const int*   adj2_row  = (const int*)d_in[6];
    const int*   adj2_col  = (const int*)d_in[7];
    const float* adj2_val  = (const float*)d_in[8];

    float* out = (float*)d_out;
    float* x1 = out;
    float* x2 = out + (size_t)N_TOT * NDIM;
    float* x3 = x2  + (size_t)N_TOT * NDIM;

    const int E = in_sizes[3];

    zero_cnt_kernel<<<208, 256>>>(W1);

    int perAdj = (E + 7) / 8;
    int pblocks = (2 * perAdj + 255) / 256;
    place_kernel<<<pblocks, 256>>>(adj_row,  adj_col,  adj_val,
                                   adj2_row, adj2_col, adj2_val, E, perAdj);

    static int smem_set = 0;
    if (!smem_set) {
        cudaFuncSetAttribute(gemm_mma_kernel,
                             cudaFuncAttributeMaxDynamicSharedMemorySize, SM_TOTAL);
        smem_set = 1;
    }
    gemm_mma_kernel<<<(N_TOT + 127) / 128, 256, SM_TOTAL>>>(emb_node, emb_attri, x1);

    spmm_kernel<<<6375, 256>>>(x1, x2, x3);

    spill_kernel<<<8, 256>>>(x1, x2, x3);
}

// round 10
// speedup vs baseline: 1.8236x; 1.0311x over previous
#include <cuda_runtime.h>
#include <cuda_bf16.h>
#include <cstdint>

#define N_NODE 100000
#define N_TOT  102000
#define NFEAT  256
#define NDIM   128
#define CAP    64
#define SPILL_MAX 8192

typedef unsigned long long u64;

// ===========================================================================
// Device scratch: ELL bins + spill + prepacked W tiles
// ===========================================================================
__device__ int  g_cnt[2][N_TOT];
__device__ u64  g_rec[2][(size_t)N_TOT * CAP];
__device__ int  g_spill_cnt;
__device__ int4 g_spill[SPILL_MAX];
// W prepacked in smem-tile byte layout: [8 k-tiles][128 rows x 64B], hi and lo
__device__ __align__(16) uint4 g_Whi_pk[4096];   // 64 KB
__device__ __align__(16) uint4 g_Wlo_pk[4096];   // 64 KB

// ---------------------------------------------------------------------------
__device__ __forceinline__ void split_pack(const float4* v, uint32_t* hp, uint32_t* lp) {
    const float* f = (const float*)v;
#pragma unroll
    for (int i = 0; i < 8; i++) {
        __nv_bfloat16 h0 = __float2bfloat16(f[2*i]);
        __nv_bfloat16 h1 = __float2bfloat16(f[2*i+1]);
        __nv_bfloat16 l0 = __float2bfloat16(f[2*i]   - __bfloat162float(h0));
        __nv_bfloat16 l1 = __float2bfloat16(f[2*i+1] - __bfloat162float(h1));
        hp[i] = (uint32_t)__bfloat16_as_ushort(h0) | ((uint32_t)__bfloat16_as_ushort(h1) << 16);
        lp[i] = (uint32_t)__bfloat16_as_ushort(l0) | ((uint32_t)__bfloat16_as_ushort(l1) << 16);
    }
}
// 8 floats -> 4 hi words + 4 lo words
__device__ __forceinline__ void split_pack8(const float4* v, uint32_t* hp, uint32_t* lp) {
    const float* f = (const float*)v;
#pragma unroll
    for (int i = 0; i < 4; i++) {
        __nv_bfloat16 h0 = __float2bfloat16(f[2*i]);
        __nv_bfloat16 h1 = __float2bfloat16(f[2*i+1]);
        __nv_bfloat16 l0 = __float2bfloat16(f[2*i]   - __bfloat162float(h0));
        __nv_bfloat16 l1 = __float2bfloat16(f[2*i+1] - __bfloat162float(h1));
        hp[i] = (uint32_t)__bfloat16_as_ushort(h0) | ((uint32_t)__bfloat16_as_ushort(h1) << 16);
        lp[i] = (uint32_t)__bfloat16_as_ushort(l0) | ((uint32_t)__bfloat16_as_ushort(l1) << 16);
    }
}

// ---------------------------------------------------------------------------
// zero counters + (block 0) prepack W into tile layout
// ---------------------------------------------------------------------------
__global__ void zero_cnt_kernel(const float* __restrict__ W) {
    int i = blockIdx.x * blockDim.x + threadIdx.x;
    int n = 2 * N_TOT;
    int stride = gridDim.x * blockDim.x;
    for (int j = i; j < n; j += stride)
        ((int*)g_cnt)[j] = 0;
    if (i == 0) g_spill_cnt = 0;

    if (blockIdx.x == 0) {
        const int t = threadIdx.x;       // 256 threads: (row, half)
        const int r = t >> 1;
        const int half = t & 1;
        const float* wrow = W + (size_t)r * NFEAT;
        char* hB = (char*)g_Whi_pk;
        char* lB = (char*)g_Wlo_pk;
        for (int ki = 0; ki < 8; ki++) {
            float4 v[4];
#pragma unroll
            for (int q = 0; q < 4; q++)
                v[q] = __ldg((const float4*)(wrow + ki * 32 + half * 16) + q);
            uint32_t hp[8], lp[8];
            split_pack(v, hp, lp);
            int sw = r & 3;
#pragma unroll
            for (int cc = 0; cc < 2; cc++) {
                int ch = (half * 2 + cc) ^ sw;
                int off = ki * 8192 + r * 64 + ch * 16;
                *(uint4*)(hB + off) = make_uint4(hp[cc*4], hp[cc*4+1], hp[cc*4+2], hp[cc*4+3]);
                *(uint4*)(lB + off) = make_uint4(lp[cc*4], lp[cc*4+1], lp[cc*4+2], lp[cc*4+3]);
            }
        }
    }
}

// ---------------------------------------------------------------------------
// ELL placement (unchanged from R6 winner)
// ---------------------------------------------------------------------------
__global__ __launch_bounds__(256) void place_kernel(
    const int* __restrict__ erow1, const int* __restrict__ ecol1, const float* __restrict__ eval1,
    const int* __restrict__ erow2, const int* __restrict__ ecol2, const float* __restrict__ eval2,
    int E, int perAdj)
{
    int idx = blockIdx.x * blockDim.x + threadIdx.x;
    int a = 0;
    if (idx >= perAdj) { a = 1; idx -= perAdj; if (idx >= perAdj) return; }
    const int*   erow = a ? erow2 : erow1;
    const int*   ecol = a ? ecol2 : ecol1;
    const float* eval = a ? eval2 : eval1;
    u64* rec = g_rec[a];
    int* cnt = g_cnt[a];

    int e0 = idx * 8;
    int nn = (e0 + 8 <= E) ? 8 : (E - e0);
    if (nn <= 0) return;

    int rr[8], cc[8]; float vv[8];
#pragma unroll
    for (int q = 0; q < 2; q++) {
        if (e0 + q * 4 + 4 <= E) {
            int4   r4 = *(const int4*)(erow + e0 + q * 4);
            int4   c4 = *(const int4*)(ecol + e0 + q * 4);
            float4 v4 = *(const float4*)(eval + e0 + q * 4);
            rr[q*4+0] = r4.x; rr[q*4+1] = r4.y; rr[q*4+2] = r4.z; rr[q*4+3] = r4.w;
            cc[q*4+0] = c4.x; cc[q*4+1] = c4.y; cc[q*4+2] = c4.z; cc[q*4+3] = c4.w;
            vv[q*4+0] = v4.x; vv[q*4+1] = v4.y; vv[q*4+2] = v4.z; vv[q*4+3] = v4.w;
        } else {
            for (int i = q * 4; i < nn; i++) {
                rr[i] = __ldg(erow + e0 + i);
                cc[i] = __ldg(ecol + e0 + i);
                vv[i] = __ldg(eval + e0 + i);
            }
        }
    }

    int pos[8];
#pragma unroll
    for (int i = 0; i < 8; i++)
        if (i < nn) pos[i] = atomicAdd(&cnt[rr[i]], 1);

#pragma unroll
    for (int i = 0; i < 8; i++) {
        if (i < nn) {
            u64 r8 = (u64)(unsigned)cc[i] | ((u64)__float_as_uint(vv[i]) << 32);
            if (pos[i] < CAP) {
                rec[(size_t)rr[i] * CAP + pos[i]] = r8;
            } else {
                int s = atomicAdd(&g_spill_cnt, 1);
                if (s < SPILL_MAX)
                    g_spill[s] = make_int4(rr[i] | (a << 30), cc[i],
                                           (int)__float_as_uint(vv[i]), 0);
            }
        }
    }
}

// ---------------------------------------------------------------------------
// SpMM v3 (unchanged from R6 winner)
// ---------------------------------------------------------------------------
__global__ __launch_bounds__(256) void spmm_kernel(
    const float* __restrict__ x1, float* __restrict__ x2, float* __restrict__ x3)
{
    const int lane  = threadIdx.x & 31;
    const int warp0 = (int)(((size_t)blockIdx.x * blockDim.x + threadIdx.x) >> 5);
    const int nw    = (gridDim.x * blockDim.x) >> 5;

    for (int gw = warp0; gw < 2 * N_TOT; gw += nw) {
        const int a = (gw >= N_TOT) ? 1 : 0;
        const int r = a ? (gw - N_TOT) : gw;

        int m = g_cnt[a][r];
        if (m > CAP) m = CAP;
        const u64* rp = g_rec[a] + (size_t)r * CAP;

        u64 myrec = 0;
        if (lane < m) myrec = __ldg(rp + lane);

        float4 acc = make_float4(0.f, 0.f, 0.f, 0.f);
        const int m1 = (m < 32) ? m : 32;
        int k = 0;

        for (; k + 4 <= m1; k += 4) {
            u64 q0 = __shfl_sync(0xffffffffu, myrec, k);
            u64 q1 = __shfl_sync(0xffffffffu, myrec, k + 1);
            u64 q2 = __shfl_sync(0xffffffffu, myrec, k + 2);
            u64 q3 = __shfl_sync(0xffffffffu, myrec, k + 3);
            float4 p0 = __ldg((const float4*)(x1 + (size_t)(unsigned)q0 * NDIM) + lane);
            float4 p1 = __ldg((const float4*)(x1 + (size_t)(unsigned)q1 * NDIM) + lane);
            float4 p2 = __ldg((const float4*)(x1 + (size_t)(unsigned)q2 * NDIM) + lane);
            float4 p3 = __ldg((const float4*)(x1 + (size_t)(unsigned)q3 * NDIM) + lane);
            float v0 = __uint_as_float((unsigned)(q0 >> 32));
            float v1 = __uint_as_float((unsigned)(q1 >> 32));
            float v2 = __uint_as_float((unsigned)(q2 >> 32));
            float v3 = __uint_as_float((unsigned)(q3 >> 32));
            acc.x = fmaf(v0, p0.x, acc.x); acc.y = fmaf(v0, p0.y, acc.y);
            acc.z = fmaf(v0, p0.z, acc.z); acc.w = fmaf(v0, p0.w, acc.w);
            acc.x = fmaf(v1, p1.x, acc.x); acc.y = fmaf(v1, p1.y, acc.y);
            acc.z = fmaf(v1, p1.z, acc.z); acc.w = fmaf(v1, p1.w, acc.w);
            acc.x = fmaf(v2, p2.x, acc.x); acc.y = fmaf(v2, p2.y, acc.y);
            acc.z = fmaf(v2, p2.z, acc.z); acc.w = fmaf(v2, p2.w, acc.w);
            acc.x = fmaf(v3, p3.x, acc.x); acc.y = fmaf(v3, p3.y, acc.y);
            acc.z = fmaf(v3, p3.z, acc.z); acc.w = fmaf(v3, p3.w, acc.w);
        }
        for (; k < m1; k++) {
            u64 q = __shfl_sync(0xffffffffu, myrec, k);
            float4 p = __ldg((const float4*)(x1 + (size_t)(unsigned)q * NDIM) + lane);
            float v = __uint_as_float((unsigned)(q >> 32));
            acc.x = fmaf(v, p.x, acc.x); acc.y = fmaf(v, p.y, acc.y);
            acc.z = fmaf(v, p.z, acc.z); acc.w = fmaf(v, p.w, acc.w);
        }
        for (; k < m; k++) {
            u64 q = __ldg(rp + k);
            float4 p = __ldg((const float4*)(x1 + (size_t)(unsigned)q * NDIM) + lane);
            float v = __uint_as_float((unsigned)(q >> 32));
            acc.x = fmaf(v, p.x, acc.x); acc.y = fmaf(v, p.y, acc.y);
            acc.z = fmaf(v, p.z, acc.z); acc.w = fmaf(v, p.w, acc.w);
        }

        float* outp = (a ? x3 : x2) + (size_t)r * NDIM;
        ((float4*)outp)[lane] = acc;
    }
}

__global__ __launch_bounds__(256) void spill_kernel(
    const float* __restrict__ x1, float* __restrict__ x2, float* __restrict__ x3)
{
    int nspill = g_spill_cnt;
    if (nspill > SPILL_MAX) nspill = SPILL_MAX;
    int lane = threadIdx.x & 31;
    int warp = (blockIdx.x * blockDim.x + threadIdx.x) >> 5;
    int nwarps = (gridDim.x * blockDim.x) >> 5;
    for (int s = warp; s < nspill; s += nwarps) {
        int4 e = g_spill[s];
        int a = (e.x >> 30) & 1;
        int r = e.x & 0x3fffffff;
        float v = __uint_as_float((unsigned)e.z);
        float4 p = __ldg((const float4*)(x1 + (size_t)e.y * NDIM) + lane);
        float* dst = (a ? x3 : x2) + (size_t)r * NDIM + lane * 4;
        asm volatile("red.global.add.v4.f32 [%0], {%1, %2, %3, %4};"
                     :: "l"(dst), "f"(p.x * v), "f"(p.y * v), "f"(p.z * v), "f"(p.w * v)
                     : "memory");
    }
}

// ===========================================================================
// bf16-split warp-MMA GEMM v3: 512 threads / 16 warps (4M x 4N), warp 32x32.
// W prepacked + resident in smem; A double-buffered; pipelined.
// ===========================================================================
__device__ __forceinline__ uint32_t smem_u32(const void* p) {
    uint32_t a;
    asm("{ .reg .u64 t; cvta.to.shared.u64 t, %1; cvt.u32.u64 %0, t; }"
        : "=r"(a) : "l"(p));
    return a;
}
__device__ __forceinline__ void ldmatrix4(uint32_t* r, uint32_t addr) {
    asm volatile("ldmatrix.sync.aligned.m8n8.x4.shared.b16 {%0,%1,%2,%3}, [%4];"
                 : "=r"(r[0]), "=r"(r[1]), "=r"(r[2]), "=r"(r[3]) : "r"(addr));
}
__device__ __forceinline__ void mma_bf16(float* d, const uint32_t* a,
                                         uint32_t b0, uint32_t b1) {
    asm volatile("mma.sync.aligned.m16n8k16.row.col.f32.bf16.bf16.f32 "
                 "{%0,%1,%2,%3},{%4,%5,%6,%7},{%8,%9},{%0,%1,%2,%3};"
                 : "+f"(d[0]), "+f"(d[1]), "+f"(d[2]), "+f"(d[3])
                 : "r"(a[0]), "r"(a[1]), "r"(a[2]), "r"(a[3]), "r"(b0), "r"(b1));
}

#define GT       512
#define SM_WHI   0
#define SM_WLO   65536
#define SM_A     131072            // stage s: +s*16384 (hi), +8192 (lo)
#define SM_TOTAL 163840            // 160 KB

__global__ __launch_bounds__(GT, 1) void gemm_mma_kernel(
    const float* __restrict__ A0, const float* __restrict__ A1,
    float* __restrict__ C)
{
    extern __shared__ __align__(128) char smem[];
    const uint32_t sb = smem_u32(smem);

    const int t    = threadIdx.x;
    const int lane = t & 31;
    const int wid  = t >> 5;
    const int warpM = (wid & 3) * 32;
    const int warpN = (wid >> 2) * 32;
    const int blockRow = blockIdx.x * 128;

    // ---- copy prepacked W into smem (8 uint4 per thread per half) ----
    {
        uint4* dh = (uint4*)(smem + SM_WHI);
        uint4* dl = (uint4*)(smem + SM_WLO);
#pragma unroll
        for (int i = 0; i < 8; i++) {
            dh[t + i * GT] = g_Whi_pk[t + i * GT];
            dl[t + i * GT] = g_Wlo_pk[t + i * GT];
        }
    }

    // loader mapping: 4 threads per row, 8 floats (one 16B chunk) each
    const int lrow = t >> 2;          // 0..127
    const int lq   = t & 3;           // chunk quarter
    const int grow = blockRow + lrow;
    const float* asrc = nullptr;
    if (grow < N_NODE)      asrc = A0 + (size_t)grow * NFEAT;
    else if (grow < N_TOT)  asrc = A1 + (size_t)(grow - N_NODE) * NFEAT;

    const int l15 = lane & 15;
    const int lk  = lane >> 4;

    float acc[2][4][4];
#pragma unroll
    for (int mt = 0; mt < 2; mt++)
#pragma unroll
        for (int nt = 0; nt < 4; nt++)
#pragma unroll
            for (int i = 0; i < 4; i++) acc[mt][nt][i] = 0.f;

    // ---- prologue: load + convert + store A tile 0 into stage 0 ----
    float4 pa[2];
#pragma unroll
    for (int i = 0; i < 2; i++)
        pa[i] = asrc ? __ldg((const float4*)(asrc + lq * 8) + i)
                     : make_float4(0.f, 0.f, 0.f, 0.f);
    {
        uint32_t hp[4], lp[4];
        split_pack8(pa, hp, lp);
        char* hB = smem + SM_A;
        char* lB = smem + SM_A + 8192;
        int ch = lq ^ (lrow & 3);
        *(uint4*)(hB + lrow * 64 + ch * 16) = make_uint4(hp[0], hp[1], hp[2], hp[3]);
        *(uint4*)(lB + lrow * 64 + ch * 16) = make_uint4(lp[0], lp[1], lp[2], lp[3]);
    }
    __syncthreads();

    // ---- main pipeline ----
    for (int ki = 0; ki < 8; ki++) {
        if (ki < 7) {
            const int kk = (ki + 1) * 32;
#pragma unroll
            for (int i = 0; i < 2; i++)
                pa[i] = asrc ? __ldg((const float4*)(asrc + kk + lq * 8) + i)
                             : make_float4(0.f, 0.f, 0.f, 0.f);
        }

        const uint32_t aHi = sb + SM_A + (uint32_t)(ki & 1) * 16384;
        const uint32_t aLo = aHi + 8192;
        const uint32_t wHi = sb + SM_WHI + (uint32_t)ki * 8192;
        const uint32_t wLo = sb + SM_WLO + (uint32_t)ki * 8192;

#pragma unroll
        for (int ks = 0; ks < 2; ks++) {
            uint32_t ah[2][4], al[2][4];
#pragma unroll
            for (int mt = 0; mt < 2; mt++) {
                int r  = warpM + mt * 16 + l15;
                int ch = ks * 2 + lk;
                uint32_t off = (uint32_t)(r * 64) + (uint32_t)((ch ^ (r & 3)) << 4);
                ldmatrix4(ah[mt], aHi + off);
                ldmatrix4(al[mt], aLo + off);
            }
#pragma unroll
            for (int np = 0; np < 2; np++) {
                int rn = warpN + np * 16 + l15;
                int ch = ks * 2 + lk;
                uint32_t off = (uint32_t)(rn * 64) + (uint32_t)((ch ^ (rn & 3)) << 4);
                uint32_t bh[4], bl[4];
                ldmatrix4(bh, wHi + off);
                ldmatrix4(bl, wLo + off);
#pragma unroll
                for (int sub = 0; sub < 2; sub++) {
                    uint32_t bh0 = bh[sub], bh1 = bh[sub + 2];
                    uint32_t bl0 = bl[sub], bl1 = bl[sub + 2];
                    int nt = np * 2 + sub;
#pragma unroll
                    for (int mt = 0; mt < 2; mt++) {
                        float* d = acc[mt][nt];
                        mma_bf16(d, al[mt], bh0, bh1);
                        mma_bf16(d, ah[mt], bl0, bl1);
                        mma_bf16(d, ah[mt], bh0, bh1);
                    }
                }
            }
        }

        if (ki < 7) {
            uint32_t hp[4], lp[4];
            split_pack8(pa, hp, lp);
            char* hB = smem + SM_A + ((ki + 1) & 1) * 16384;
            char* lB = hB + 8192;
            int ch = lq ^ (lrow & 3);
            *(uint4*)(hB + lrow * 64 + ch * 16) = make_uint4(hp[0], hp[1], hp[2], hp[3]);
            *(uint4*)(lB + lrow * 64 + ch * 16) = make_uint4(lp[0], lp[1], lp[2], lp[3]);
        }
        __syncthreads();
    }

    // ---- epilogue ----
    const int erow = blockRow + warpM + (lane >> 2);
    const int ecol0 = (lane & 3) * 2;
#pragma unroll
    for (int mt = 0; mt < 2; mt++) {
        int r0 = erow + mt * 16;
#pragma unroll
        for (int nt = 0; nt < 4; nt++) {
            const float* d = acc[mt][nt];
            int col = warpN + nt * 8 + ecol0;
            if (r0 < N_TOT)
                *(float2*)(C + (size_t)r0 * NDIM + col) = make_float2(d[0], d[1]);
            if (r0 + 8 < N_TOT)
                *(float2*)(C + (size_t)(r0 + 8) * NDIM + col) = make_float2(d[2], d[3]);
        }
    }
}

// ===========================================================================
extern "C" void kernel_launch(void* const* d_in, const int* in_sizes, int n_in,
                              void* d_out, int out_size)
{
    const float* emb_node  = (const float*)d_in[0];
    const float* emb_attri = (const float*)d_in[1];
    const float* W1        = (const float*)d_in[2];
    const int*   adj_row   = (const int*)d_in[3];
    const int*   adj_col   = (const int*)d_in[4];
    const float* adj_val   = (const float*)d_in[5];
    const int*   adj2_row  = (const int*)d_in[6];
    const int*   adj2_col  = (const int*)d_in[7];
    const float* adj2_val  = (const float*)d_in[8];

    float* out = (float*)d_out;
    float* x1 = out;
    float* x2 = out + (size_t)N_TOT * NDIM;
    float* x3 = x2  + (size_t)N_TOT * NDIM;

    const int E = in_sizes[3];

    // one-time host-side objects (no device memory)
    static cudaStream_t s2 = nullptr;
    static cudaEvent_t evFork = nullptr, evJoin = nullptr;
    if (!s2) {
        cudaStreamCreateWithFlags(&s2, cudaStreamNonBlocking);
        cudaEventCreateWithFlags(&evFork, cudaEventDisableTiming);
        cudaEventCreateWithFlags(&evJoin, cudaEventDisableTiming);
        cudaFuncSetAttribute(gemm_mma_kernel,
                             cudaFuncAttributeMaxDynamicSharedMemorySize, SM_TOTAL);
    }

    zero_cnt_kernel<<<208, 256>>>(W1);

    // fork: place on s2, gemm on main — independent subsystems
    cudaEventRecord(evFork, 0);
    cudaStreamWaitEvent(s2, evFork, 0);

    int perAdj = (E + 7) / 8;
    int pblocks = (2 * perAdj + 255) / 256;
    place_kernel<<<pblocks, 256, 0, s2>>>(adj_row,  adj_col,  adj_val,
                                          adj2_row, adj2_col, adj2_val, E, perAdj);

    gemm_mma_kernel<<<(N_TOT + 127) / 128, GT, SM_TOTAL>>>(emb_node, emb_attri, x1);

    // join: spmm needs both place (s2) and gemm (main)
    cudaEventRecord(evJoin, s2);
    cudaStreamWaitEvent(0, evJoin, 0);

    spmm_kernel<<<6375, 256>>>(x1, x2, x3);

    spill_kernel<<<8, 256>>>(x1, x2, x3);
}

// round 12
// speedup vs baseline: 1.8906x; 1.0367x over previous
#include <cuda_runtime.h>
#include <cuda_bf16.h>
#include <cuda_fp16.h>
#include <cstdint>

#define N_NODE 100000
#define N_TOT  102000
#define NFEAT  256
#define NDIM   128
#define CAP    64
#define SPILL_MAX 8192

typedef unsigned long long u64;

// ===========================================================================
// Device scratch
// ===========================================================================
__device__ int  g_cnt[2][N_TOT];
__device__ u64  g_rec[2][(size_t)N_TOT * CAP];
__device__ int  g_spill_cnt;
__device__ int4 g_spill[SPILL_MAX];
__device__ __align__(16) uint4 g_Whi_pk[4096];   // 64 KB prepacked W hi
__device__ __align__(16) uint4 g_Wlo_pk[4096];   // 64 KB prepacked W lo
__device__ __align__(16) __half g_x1h[(size_t)N_TOT * NDIM];  // 26 MB fp16 x1

// ---------------------------------------------------------------------------
__device__ __forceinline__ void split_pack(const float4* v, uint32_t* hp, uint32_t* lp) {
    const float* f = (const float*)v;
#pragma unroll
    for (int i = 0; i < 8; i++) {
        __nv_bfloat16 h0 = __float2bfloat16(f[2*i]);
        __nv_bfloat16 h1 = __float2bfloat16(f[2*i+1]);
        __nv_bfloat16 l0 = __float2bfloat16(f[2*i]   - __bfloat162float(h0));
        __nv_bfloat16 l1 = __float2bfloat16(f[2*i+1] - __bfloat162float(h1));
        hp[i] = (uint32_t)__bfloat16_as_ushort(h0) | ((uint32_t)__bfloat16_as_ushort(h1) << 16);
        lp[i] = (uint32_t)__bfloat16_as_ushort(l0) | ((uint32_t)__bfloat16_as_ushort(l1) << 16);
    }
}
__device__ __forceinline__ void split_pack8(const float4* v, uint32_t* hp, uint32_t* lp) {
    const float* f = (const float*)v;
#pragma unroll
    for (int i = 0; i < 4; i++) {
        __nv_bfloat16 h0 = __float2bfloat16(f[2*i]);
        __nv_bfloat16 h1 = __float2bfloat16(f[2*i+1]);
        __nv_bfloat16 l0 = __float2bfloat16(f[2*i]   - __bfloat162float(h0));
        __nv_bfloat16 l1 = __float2bfloat16(f[2*i+1] - __bfloat162float(h1));
        hp[i] = (uint32_t)__bfloat16_as_ushort(h0) | ((uint32_t)__bfloat16_as_ushort(h1) << 16);
        lp[i] = (uint32_t)__bfloat16_as_ushort(l0) | ((uint32_t)__bfloat16_as_ushort(l1) << 16);
    }
}

// ---------------------------------------------------------------------------
// zero counters + (block 0) prepack W
// ---------------------------------------------------------------------------
__global__ void zero_cnt_kernel(const float* __restrict__ W) {
    int i = blockIdx.x * blockDim.x + threadIdx.x;
    int n = 2 * N_TOT;
    int stride = gridDim.x * blockDim.x;
    for (int j = i; j < n; j += stride)
        ((int*)g_cnt)[j] = 0;
    if (i == 0) g_spill_cnt = 0;

    if (blockIdx.x == 0) {
        const int t = threadIdx.x;
        const int r = t >> 1;
        const int half = t & 1;
        const float* wrow = W + (size_t)r * NFEAT;
        char* hB = (char*)g_Whi_pk;
        char* lB = (char*)g_Wlo_pk;
        for (int ki = 0; ki < 8; ki++) {
            float4 v[4];
#pragma unroll
            for (int q = 0; q < 4; q++)
                v[q] = __ldg((const float4*)(wrow + ki * 32 + half * 16) + q);
            uint32_t hp[8], lp[8];
            split_pack(v, hp, lp);
            int sw = r & 3;
#pragma unroll
            for (int cc = 0; cc < 2; cc++) {
                int ch = (half * 2 + cc) ^ sw;
                int off = ki * 8192 + r * 64 + ch * 16;
                *(uint4*)(hB + off) = make_uint4(hp[cc*4], hp[cc*4+1], hp[cc*4+2], hp[cc*4+3]);
                *(uint4*)(lB + off) = make_uint4(lp[cc*4], lp[cc*4+1], lp[cc*4+2], lp[cc*4+3]);
            }
        }
    }
}

// ---------------------------------------------------------------------------
// ELL placement (unchanged)
// ---------------------------------------------------------------------------
__global__ __launch_bounds__(256) void place_kernel(
    const int* __restrict__ erow1, const int* __restrict__ ecol1, const float* __restrict__ eval1,
    const int* __restrict__ erow2, const int* __restrict__ ecol2, const float* __restrict__ eval2,
    int E, int perAdj)
{
    int idx = blockIdx.x * blockDim.x + threadIdx.x;
    int a = 0;
    if (idx >= perAdj) { a = 1; idx -= perAdj; if (idx >= perAdj) return; }
    const int*   erow = a ? erow2 : erow1;
    const int*   ecol = a ? ecol2 : ecol1;
    const float* eval = a ? eval2 : eval1;
    u64* rec = g_rec[a];
    int* cnt = g_cnt[a];

    int e0 = idx * 8;
    int nn = (e0 + 8 <= E) ? 8 : (E - e0);
    if (nn <= 0) return;

    int rr[8], cc[8]; float vv[8];
#pragma unroll
    for (int q = 0; q < 2; q++) {
        if (e0 + q * 4 + 4 <= E) {
            int4   r4 = *(const int4*)(erow + e0 + q * 4);
            int4   c4 = *(const int4*)(ecol + e0 + q * 4);
            float4 v4 = *(const float4*)(eval + e0 + q * 4);
            rr[q*4+0] = r4.x; rr[q*4+1] = r4.y; rr[q*4+2] = r4.z; rr[q*4+3] = r4.w;
            cc[q*4+0] = c4.x; cc[q*4+1] = c4.y; cc[q*4+2] = c4.z; cc[q*4+3] = c4.w;
            vv[q*4+0] = v4.x; vv[q*4+1] = v4.y; vv[q*4+2] = v4.z; vv[q*4+3] = v4.w;
        } else {
            for (int i = q * 4; i < nn; i++) {
                rr[i] = __ldg(erow + e0 + i);
                cc[i] = __ldg(ecol + e0 + i);
                vv[i] = __ldg(eval + e0 + i);
            }
        }
    }

    int pos[8];
#pragma unroll
    for (int i = 0; i < 8; i++)
        if (i < nn) pos[i] = atomicAdd(&cnt[rr[i]], 1);

#pragma unroll
    for (int i = 0; i < 8; i++) {
        if (i < nn) {
            u64 r8 = (u64)(unsigned)cc[i] | ((u64)__float_as_uint(vv[i]) << 32);
            if (pos[i] < CAP) {
                rec[(size_t)rr[i] * CAP + pos[i]] = r8;
            } else {
                int s = atomicAdd(&g_spill_cnt, 1);
                if (s < SPILL_MAX)
                    g_spill[s] = make_int4(rr[i] | (a << 30), cc[i],
                                           (int)__float_as_uint(vv[i]), 0);
            }
        }
    }
}

// ---------------------------------------------------------------------------
// SpMM v4: fp16 gathers (uint2/lane), MLP=8, dual accumulator chains.
// ---------------------------------------------------------------------------
__global__ __launch_bounds__(256) void spmm_kernel(
    float* __restrict__ x2, float* __restrict__ x3)
{
    const int lane  = threadIdx.x & 31;
    const int warp0 = (int)(((size_t)blockIdx.x * blockDim.x + threadIdx.x) >> 5);
    const int nw    = (gridDim.x * blockDim.x) >> 5;
    const __half* xh = g_x1h;

    for (int gw = warp0; gw < 2 * N_TOT; gw += nw) {
        const int a = (gw >= N_TOT) ? 1 : 0;
        const int r = a ? (gw - N_TOT) : gw;

        int m = g_cnt[a][r];
        if (m > CAP) m = CAP;
        const u64* rp = g_rec[a] + (size_t)r * CAP;

        u64 myrec = 0;
        if (lane < m) myrec = __ldg(rp + lane);

        float4 accA = make_float4(0.f, 0.f, 0.f, 0.f);
        float4 accB = make_float4(0.f, 0.f, 0.f, 0.f);
        const int m1 = (m < 32) ? m : 32;
        int k = 0;

        for (; k + 8 <= m1; k += 8) {
            uint2 u[8]; float v[8];
#pragma unroll
            for (int i = 0; i < 8; i++) {
                u64 q = __shfl_sync(0xffffffffu, myrec, k + i);
                v[i] = __uint_as_float((unsigned)(q >> 32));
                u[i] = __ldg((const uint2*)(xh + (size_t)(unsigned)q * NDIM) + lane);
            }
#pragma unroll
            for (int i = 0; i < 8; i++) {
                float2 f01 = __half22float2(*(const __half2*)&u[i].x);
                float2 f23 = __half22float2(*(const __half2*)&u[i].y);
                float4* A = (i & 1) ? &accB : &accA;
                A->x = fmaf(v[i], f01.x, A->x);
                A->y = fmaf(v[i], f01.y, A->y);
                A->z = fmaf(v[i], f23.x, A->z);
                A->w = fmaf(v[i], f23.y, A->w);
            }
        }
        for (; k < m1; k++) {
            u64 q = __shfl_sync(0xffffffffu, myrec, k);
            float v = __uint_as_float((unsigned)(q >> 32));
            uint2 u = __ldg((const uint2*)(xh + (size_t)(unsigned)q * NDIM) + lane);
            float2 f01 = __half22float2(*(const __half2*)&u.x);
            float2 f23 = __half22float2(*(const __half2*)&u.y);
            accA.x = fmaf(v, f01.x, accA.x);
            accA.y = fmaf(v, f01.y, accA.y);
            accA.z = fmaf(v, f23.x, accA.z);
            accA.w = fmaf(v, f23.y, accA.w);
        }
        for (; k < m; k++) {           // rare: degree > 32
            u64 q = __ldg(rp + k);
            float v = __uint_as_float((unsigned)(q >> 32));
            uint2 u = __ldg((const uint2*)(xh + (size_t)(unsigned)q * NDIM) + lane);
            float2 f01 = __half22float2(*(const __half2*)&u.x);
            float2 f23 = __half22float2(*(const __half2*)&u.y);
            accA.x = fmaf(v, f01.x, accA.x);
            accA.y = fmaf(v, f01.y, accA.y);
            accA.z = fmaf(v, f23.x, accA.z);
            accA.w = fmaf(v, f23.y, accA.w);
        }

        float4 acc;
        acc.x = accA.x + accB.x; acc.y = accA.y + accB.y;
        acc.z = accA.z + accB.z; acc.w = accA.w + accB.w;
        float* outp = (a ? x3 : x2) + (size_t)r * NDIM;
        ((float4*)outp)[lane] = acc;
    }
}

__global__ __launch_bounds__(256) void spill_kernel(
    const float* __restrict__ x1, float* __restrict__ x2, float* __restrict__ x3)
{
    int nspill = g_spill_cnt;
    if (nspill > SPILL_MAX) nspill = SPILL_MAX;
    int lane = threadIdx.x & 31;
    int warp = (blockIdx.x * blockDim.x + threadIdx.x) >> 5;
    int nwarps = (gridDim.x * blockDim.x) >> 5;
    for (int s = warp; s < nspill; s += nwarps) {
        int4 e = g_spill[s];
        int a = (e.x >> 30) & 1;
        int r = e.x & 0x3fffffff;
        float v = __uint_as_float((unsigned)e.z);
        float4 p = __ldg((const float4*)(x1 + (size_t)e.y * NDIM) + lane);
        float* dst = (a ? x3 : x2) + (size_t)r * NDIM + lane * 4;
        asm volatile("red.global.add.v4.f32 [%0], {%1, %2, %3, %4};"
                     :: "l"(dst), "f"(p.x * v), "f"(p.y * v), "f"(p.z * v), "f"(p.w * v)
                     : "memory");
    }
}

// ===========================================================================
// bf16-split warp-MMA GEMM + fp16 x1 copy in epilogue
// ===========================================================================
__device__ __forceinline__ uint32_t smem_u32(const void* p) {
    uint32_t a;
    asm("{ .reg .u64 t; cvta.to.shared.u64 t, %1; cvt.u32.u64 %0, t; }"
        : "=r"(a) : "l"(p));
    return a;
}
__device__ __forceinline__ void ldmatrix4(uint32_t* r, uint32_t addr) {
    asm volatile("ldmatrix.sync.aligned.m8n8.x4.shared.b16 {%0,%1,%2,%3}, [%4];"
                 : "=r"(r[0]), "=r"(r[1]), "=r"(r[2]), "=r"(r[3]) : "r"(addr));
}
__device__ __forceinline__ void mma_bf16(float* d, const uint32_t* a,
                                         uint32_t b0, uint32_t b1) {
    asm volatile("mma.sync.aligned.m16n8k16.row.col.f32.bf16.bf16.f32 "
                 "{%0,%1,%2,%3},{%4,%5,%6,%7},{%8,%9},{%0,%1,%2,%3};"
                 : "+f"(d[0]), "+f"(d[1]), "+f"(d[2]), "+f"(d[3])
                 : "r"(a[0]), "r"(a[1]), "r"(a[2]), "r"(a[3]), "r"(b0), "r"(b1));
}

#define GT       512
#define SM_WHI   0
#define SM_WLO   65536
#define SM_A     131072
#define SM_TOTAL 163840

__global__ __launch_bounds__(GT, 1) void gemm_mma_kernel(
    const float* __restrict__ A0, const float* __restrict__ A1,
    float* __restrict__ C)
{
    extern __shared__ __align__(128) char smem[];
    const uint32_t sb = smem_u32(smem);

    const int t    = threadIdx.x;
    const int lane = t & 31;
    const int wid  = t >> 5;
    const int warpM = (wid & 3) * 32;
    const int warpN = (wid >> 2) * 32;
    const int blockRow = blockIdx.x * 128;

    {
        uint4* dh = (uint4*)(smem + SM_WHI);
        uint4* dl = (uint4*)(smem + SM_WLO);
#pragma unroll
        for (int i = 0; i < 8; i++) {
            dh[t + i * GT] = g_Whi_pk[t + i * GT];
            dl[t + i * GT] = g_Wlo_pk[t + i * GT];
        }
    }

    const int lrow = t >> 2;
    const int lq   = t & 3;
    const int grow = blockRow + lrow;
    const float* asrc = nullptr;
    if (grow < N_NODE)      asrc = A0 + (size_t)grow * NFEAT;
    else if (grow < N_TOT)  asrc = A1 + (size_t)(grow - N_NODE) * NFEAT;

    const int l15 = lane & 15;
    const int lk  = lane >> 4;

    float acc[2][4][4];
#pragma unroll
    for (int mt = 0; mt < 2; mt++)
#pragma unroll
        for (int nt = 0; nt < 4; nt++)
#pragma unroll
            for (int i = 0; i < 4; i++) acc[mt][nt][i] = 0.f;

    float4 pa[2];
#pragma unroll
    for (int i = 0; i < 2; i++)
        pa[i] = asrc ? __ldg((const float4*)(asrc + lq * 8) + i)
                     : make_float4(0.f, 0.f, 0.f, 0.f);
    {
        uint32_t hp[4], lp[4];
        split_pack8(pa, hp, lp);
        char* hB = smem + SM_A;
        char* lB = smem + SM_A + 8192;
        int ch = lq ^ (lrow & 3);
        *(uint4*)(hB + lrow * 64 + ch * 16) = make_uint4(hp[0], hp[1], hp[2], hp[3]);
        *(uint4*)(lB + lrow * 64 + ch * 16) = make_uint4(lp[0], lp[1], lp[2], lp[3]);
    }
    __syncthreads();

    for (int ki = 0; ki < 8; ki++) {
        if (ki < 7) {
            const int kk = (ki + 1) * 32;
#pragma unroll
            for (int i = 0; i < 2; i++)
                pa[i] = asrc ? __ldg((const float4*)(asrc + kk + lq * 8) + i)
                             : make_float4(0.f, 0.f, 0.f, 0.f);
        }

        const uint32_t aHi = sb + SM_A + (uint32_t)(ki & 1) * 16384;
        const uint32_t aLo = aHi + 8192;
        const uint32_t wHi = sb + SM_WHI + (uint32_t)ki * 8192;
        const uint32_t wLo = sb + SM_WLO + (uint32_t)ki * 8192;

#pragma unroll
        for (int ks = 0; ks < 2; ks++) {
            uint32_t ah[2][4], al[2][4];
#pragma unroll
            for (int mt = 0; mt < 2; mt++) {
                int r  = warpM + mt * 16 + l15;
                int ch = ks * 2 + lk;
                uint32_t off = (uint32_t)(r * 64) + (uint32_t)((ch ^ (r & 3)) << 4);
                ldmatrix4(ah[mt], aHi + off);
                ldmatrix4(al[mt], aLo + off);
            }
#pragma unroll
            for (int np = 0; np < 2; np++) {
                int rn = warpN + np * 16 + l15;
                int ch = ks * 2 + lk;
                uint32_t off = (uint32_t)(rn * 64) + (uint32_t)((ch ^ (rn & 3)) << 4);
                uint32_t bh[4], bl[4];
                ldmatrix4(bh, wHi + off);
                ldmatrix4(bl, wLo + off);
#pragma unroll
                for (int sub = 0; sub < 2; sub++) {
                    uint32_t bh0 = bh[sub], bh1 = bh[sub + 2];
                    uint32_t bl0 = bl[sub], bl1 = bl[sub + 2];
                    int nt = np * 2 + sub;
#pragma unroll
                    for (int mt = 0; mt < 2; mt++) {
                        float* d = acc[mt][nt];
                        mma_bf16(d, al[mt], bh0, bh1);
                        mma_bf16(d, ah[mt], bl0, bl1);
                        mma_bf16(d, ah[mt], bh0, bh1);
                    }
                }
            }
        }

        if (ki < 7) {
            uint32_t hp[4], lp[4];
            split_pack8(pa, hp, lp);
            char* hB = smem + SM_A + ((ki + 1) & 1) * 16384;
            char* lB = hB + 8192;
            int ch = lq ^ (lrow & 3);
            *(uint4*)(hB + lrow * 64 + ch * 16) = make_uint4(hp[0], hp[1], hp[2], hp[3]);
            *(uint4*)(lB + lrow * 64 + ch * 16) = make_uint4(lp[0], lp[1], lp[2], lp[3]);
        }
        __syncthreads();
    }

    // epilogue: fp32 x1 + fp16 copy
    const int erow = blockRow + warpM + (lane >> 2);
    const int ecol0 = (lane & 3) * 2;
#pragma unroll
    for (int mt = 0; mt < 2; mt++) {
        int r0 = erow + mt * 16;
#pragma unroll
        for (int nt = 0; nt < 4; nt++) {
            const float* d = acc[mt][nt];
            int col = warpN + nt * 8 + ecol0;
            if (r0 < N_TOT) {
                *(float2*)(C + (size_t)r0 * NDIM + col) = make_float2(d[0], d[1]);
                *(__half2*)(g_x1h + (size_t)r0 * NDIM + col) =
                    __floats2half2_rn(d[0], d[1]);
            }
            if (r0 + 8 < N_TOT) {
                *(float2*)(C + (size_t)(r0 + 8) * NDIM + col) = make_float2(d[2], d[3]);
                *(__half2*)(g_x1h + (size_t)(r0 + 8) * NDIM + col) =
                    __floats2half2_rn(d[2], d[3]);
            }
        }
    }
}

// ===========================================================================
extern "C" void kernel_launch(void* const* d_in, const int* in_sizes, int n_in,
                              void* d_out, int out_size)
{
    const float* emb_node  = (const float*)d_in[0];
    const float* emb_attri = (const float*)d_in[1];
    const float* W1        = (const float*)d_in[2];
    const int*   adj_row   = (const int*)d_in[3];
    const int*   adj_col   = (const int*)d_in[4];
    const float* adj_val   = (const float*)d_in[5];
    const int*   adj2_row  = (const int*)d_in[6];
    const int*   adj2_col  = (const int*)d_in[7];
    const float* adj2_val  = (const float*)d_in[8];

    float* out = (float*)d_out;
    float* x1 = out;
    float* x2 = out + (size_t)N_TOT * NDIM;
    float* x3 = x2  + (size_t)N_TOT * NDIM;

    const int E = in_sizes[3];

    static cudaStream_t s2 = nullptr;
    static cudaEvent_t evFork = nullptr, evJoin = nullptr;
    if (!s2) {
        cudaStreamCreateWithFlags(&s2, cudaStreamNonBlocking);
        cudaEventCreateWithFlags(&evFork, cudaEventDisableTiming);
        cudaEventCreateWithFlags(&evJoin, cudaEventDisableTiming);
        cudaFuncSetAttribute(gemm_mma_kernel,
                             cudaFuncAttributeMaxDynamicSharedMemorySize, SM_TOTAL);
    }

    zero_cnt_kernel<<<208, 256>>>(W1);

    cudaEventRecord(evFork, 0);
    cudaStreamWaitEvent(s2, evFork, 0);

    int perAdj = (E + 7) / 8;
    int pblocks = (2 * perAdj + 255) / 256;
    place_kernel<<<pblocks, 256, 0, s2>>>(adj_row,  adj_col,  adj_val,
                                          adj2_row, adj2_col, adj2_val, E, perAdj);

    gemm_mma_kernel<<<(N_TOT + 127) / 128, GT, SM_TOTAL>>>(emb_node, emb_attri, x1);

    cudaEventRecord(evJoin, s2);
    cudaStreamWaitEvent(0, evJoin, 0);

    spmm_kernel<<<6375, 256>>>(x2, x3);

    spill_kernel<<<8, 256>>>(x1, x2, x3);
}